// round 9
// baseline (speedup 1.0000x reference)
#include <cuda_runtime.h>
#include <cuda_bf16.h>
#include <mma.h>
#include <math.h>
#include <stdint.h>

using namespace nvcuda;

#define NN 50000
#define NE 800000
#define DD 128
#define OUT_ELEMS (NN * DD)
#define BM 64
#define GEMM_BLOCKS ((NN + BM - 1) / BM)
#define SCAN_B ((NN + 255) / 256)
#define EPT 4
#define EDGE_BLOCKS ((NE / EPT + 255) / 256)

// ---------------- device scratch (zero at load; every call restores zeros) --------
__device__ __align__(16) float g_mean[NN * DD];
__device__ __align__(16) float g_h[NN * DD];
__device__ __align__(16) float g_emb[NN * DD];
__device__ int   g_deg[NN];          // zeroed by k_scan after consumption
__device__ int   g_off[NN + 1];
__device__ int   g_cur[NN];
__device__ int   g_col[NE];
__device__ unsigned char g_yb[NN];
__device__ float g_lp;               // zeroed by k_final after consumption
__device__ float g_ln;
__device__ int   g_npos;
__device__ unsigned long long g_lb[SCAN_B];  // zeroed by k_fill after scan
// plain bf16 weight images: [5 weights][hi=0/lo=1][k*128+n]
__device__ __align__(16) unsigned short g_Bimg[5][2][DD * DD];

// ---------------- per-block dtype detection ----------------
__device__ __forceinline__ int detect_e64(const void* edge) {
    __shared__ int s64;
    if (threadIdx.x == 0) s64 = 1;
    __syncthreads();
    if (threadIdx.x < 256) {
        long long v = ((const long long*)edge)[threadIdx.x];
        if (v < 0 || v >= NN) atomicAnd(&s64, 0);
    }
    __syncthreads();
    return s64;
}

__device__ __forceinline__ int edge_at(const void* edge, int idx, int e64) {
    if (e64) return (int)((const long long*)edge)[idx];
    return ((const int*)edge)[idx];
}

// ---------------- k_prep: detect + y normalize + weight split + degree ------------
__global__ void k_prep(const void* __restrict__ yv, const void* __restrict__ edge,
                       const float* __restrict__ W0, const float* __restrict__ W1,
                       const float* __restrict__ W2, const float* __restrict__ W3,
                       const float* __restrict__ W4) {
    __shared__ int s32;
    if (threadIdx.x == 0) s32 = 1;
    int e64 = detect_e64(edge);
    if (threadIdx.x < 64) {
        unsigned int w = ((const unsigned int*)yv)[threadIdx.x];
        if (w > 1u) atomicAnd(&s32, 0);
    }
    __syncthreads();
    int y32 = s32;

    int i = blockIdx.x * blockDim.x + threadIdx.x;
    int v = 0;
    if (i < NN) {
        if (y32) v = (((const int*)yv)[i] != 0) ? 1 : 0;
        else     v = (((const unsigned char*)yv)[i] != 0) ? 1 : 0;
        g_yb[i] = (unsigned char)v;
    }
    #pragma unroll
    for (int o = 16; o; o >>= 1) v += __shfl_down_sync(0xffffffffu, v, o);
    if ((threadIdx.x & 31) == 0 && v) atomicAdd(&g_npos, v);

    if (i < 5 * DD * DD) {
        int w = i / (DD * DD);
        int r = i % (DD * DD);
        const float* Wm = (w == 0) ? W0 : (w == 1) ? W1 : (w == 2) ? W2 : (w == 3) ? W3 : W4;
        float val = Wm[r];
        __nv_bfloat16 hi = __float2bfloat16(val);
        g_Bimg[w][0][r] = __bfloat16_as_ushort(hi);
        g_Bimg[w][1][r] = __bfloat16_as_ushort(__float2bfloat16(val - __bfloat162float(hi)));
    }

    int base = i * EPT;
    int d[EPT];
    #pragma unroll
    for (int j = 0; j < EPT; j++)
        d[j] = (base + j < NE) ? edge_at(edge, NE + base + j, e64) : -1;
    #pragma unroll
    for (int j = 0; j < EPT; j++)
        if (d[j] >= 0 && d[j] < NN) atomicAdd(&g_deg[d[j]], 1);
}

// ---------------- decoupled-lookback scan (zeroes g_deg after reading) ------------
__global__ void k_scan() {
    __shared__ int sh[256];
    __shared__ int s_ex;
    int b = blockIdx.x, t = threadIdx.x;
    int i = b * 256 + t;
    int v = (i < NN) ? g_deg[i] : 0;
    sh[t] = v;
    __syncthreads();
    for (int o = 1; o < 256; o <<= 1) {
        int add = (t >= o) ? sh[t - o] : 0;
        __syncthreads();
        sh[t] += add;
        __syncthreads();
    }
    int T = sh[255];
    if (t == 0) {
        if (b == 0) {
            atomicExch(&g_lb[0], (2ULL << 32) | (unsigned)T);
            s_ex = 0;
        } else {
            atomicExch(&g_lb[b], (1ULL << 32) | (unsigned)T);
            int ex = 0;
            for (int j = b - 1; j >= 0;) {
                unsigned long long w;
                do { w = atomicAdd(&g_lb[j], 0ULL); } while ((w >> 32) == 0ULL);
                if ((w >> 32) == 2ULL) { ex += (int)(unsigned)w; break; }
                ex += (int)(unsigned)w;
                j--;
            }
            atomicExch(&g_lb[b], (2ULL << 32) | (unsigned)(ex + T));
            s_ex = ex;
        }
    }
    __syncthreads();
    int ex = s_ex;
    if (i < NN) {
        int off = ex + sh[t] - v;
        g_off[i] = off;
        g_cur[i] = off;
        g_deg[i] = 0;                 // restore invariant
    }
    if (b == SCAN_B - 1 && t == 0) g_off[NN] = ex + T;
}

// ---------------- CSR fill (EPT edges/thread; zeroes g_lb) ----------------
__global__ void k_fill(const void* __restrict__ edge) {
    int e64 = detect_e64(edge);
    int i = blockIdx.x * blockDim.x + threadIdx.x;
    if (i < SCAN_B) g_lb[i] = 0ULL;   // restore invariant
    int base = i * EPT;
    int s[EPT], d[EPT];
    #pragma unroll
    for (int j = 0; j < EPT; j++) {
        if (base + j < NE) {
            d[j] = edge_at(edge, NE + base + j, e64);
            s[j] = edge_at(edge, base + j, e64);
        } else { d[j] = -1; s[j] = 0; }
    }
    #pragma unroll
    for (int j = 0; j < EPT; j++) {
        if (d[j] >= 0 && d[j] < NN && s[j] >= 0 && s[j] < NN) {
            int p = atomicAdd(&g_cur[d[j]], 1);
            g_col[p] = s[j];
        }
    }
}

// ---------------- pipelined WMMA bf16x3 fused GEMM with inline mean phase ---------
#define ALD 40
#define BLD 136
typedef wmma::fragment<wmma::accumulator, 16, 16, 16, float> AccFrag;

struct Pref {
    float4 a0, a1;
    uint4 b[4];
};

__device__ __forceinline__ void pf_load(Pref& p, const float* __restrict__ Asrc,
                                        int wsel, int c, int m0, int tid) {
    {
        int row = tid >> 3, q = tid & 7;
        int gm = m0 + row;
        p.a0 = (gm < NN) ? *(const float4*)&Asrc[(size_t)gm * DD + c * 32 + q * 4]
                         : make_float4(0.f, 0.f, 0.f, 0.f);
    }
    {
        int id = tid + 256;
        int row = id >> 3, q = id & 7;
        int gm = m0 + row;
        p.a1 = (gm < NN) ? *(const float4*)&Asrc[(size_t)gm * DD + c * 32 + q * 4]
                         : make_float4(0.f, 0.f, 0.f, 0.f);
    }
    #pragma unroll
    for (int it = 0; it < 4; it++) {
        int hl = it >> 1;
        int id = tid + (it & 1) * 256;
        int k = id >> 4, c16 = id & 15;
        p.b[it] = ((const uint4*)&g_Bimg[wsel][hl][(c * 32 + k) * DD])[c16];
    }
}

__device__ __forceinline__ void pf_store(const Pref& p, __nv_bfloat16 (*As)[BM * ALD],
                                         __nv_bfloat16 (*Bs)[32 * BLD], int tid) {
    #pragma unroll
    for (int it = 0; it < 2; it++) {
        int id = tid + it * 256;
        int row = id >> 3, q = id & 7;
        float4 v = it ? p.a1 : p.a0;
        float vv[4] = {v.x, v.y, v.z, v.w};
        #pragma unroll
        for (int j = 0; j < 4; j++) {
            __nv_bfloat16 hi = __float2bfloat16(vv[j]);
            As[0][row * ALD + q * 4 + j] = hi;
            As[1][row * ALD + q * 4 + j] = __float2bfloat16(vv[j] - __bfloat162float(hi));
        }
    }
    #pragma unroll
    for (int it = 0; it < 4; it++) {
        int hl = it >> 1;
        int id = tid + (it & 1) * 256;
        int k = id >> 4, c16 = id & 15;
        ((uint4*)&Bs[hl][k * BLD])[c16] = p.b[it];
    }
}

__device__ __forceinline__ void mma_chunk(__nv_bfloat16 (*As)[BM * ALD],
                                          __nv_bfloat16 (*Bs)[32 * BLD],
                                          AccFrag (&acc)[4], int warp_m, int warp_n) {
    #pragma unroll
    for (int ks = 0; ks < 2; ks++) {
        wmma::fragment<wmma::matrix_a, 16, 16, 16, __nv_bfloat16, wmma::row_major> a_hi, a_lo;
        wmma::load_matrix_sync(a_hi, &As[0][warp_m * 16 * ALD + ks * 16], ALD);
        wmma::load_matrix_sync(a_lo, &As[1][warp_m * 16 * ALD + ks * 16], ALD);
        #pragma unroll
        for (int nt = 0; nt < 4; nt++) {
            int nb = warp_n * 64 + nt * 16;
            wmma::fragment<wmma::matrix_b, 16, 16, 16, __nv_bfloat16, wmma::row_major> b_hi, b_lo;
            wmma::load_matrix_sync(b_hi, &Bs[0][ks * 16 * BLD + nb], BLD);
            wmma::load_matrix_sync(b_lo, &Bs[1][ks * 16 * BLD + nb], BLD);
            wmma::mma_sync(acc[nt], a_hi, b_hi, acc[nt]);
            wmma::mma_sync(acc[nt], a_hi, b_lo, acc[nt]);
            wmma::mma_sync(acc[nt], a_lo, b_hi, acc[nt]);
        }
    }
}

__device__ __forceinline__ void gemm_pipeline(
    const float* __restrict__ src0, int wsel0,
    const float* __restrict__ src1, int wsel1, int nsrc,
    int m0, __nv_bfloat16 (*As)[BM * ALD], __nv_bfloat16 (*Bs)[32 * BLD],
    AccFrag (&acc)[4], int tid, int warp_m, int warp_n) {
    Pref p;
    pf_load(p, src0, wsel0, 0, m0, tid);
    int T = nsrc * 4;
    for (int t = 0; t < T; t++) {
        pf_store(p, As, Bs, tid);
        __syncthreads();
        if (t + 1 < T) {
            const float* nptr = ((t + 1) >> 2) ? src1 : src0;
            int nwsel = ((t + 1) >> 2) ? wsel1 : wsel0;
            pf_load(p, nptr, nwsel, (t + 1) & 3, m0, tid);
        }
        mma_chunk(As, Bs, acc, warp_m, warp_n);
        __syncthreads();
    }
}

// inline mean phase: this block's BM rows, 1 warp per row, float4 lanes
__device__ __forceinline__ void mean_phase(const float* __restrict__ gsrc,
                                           int m0, int wid, int lane) {
    const float4* __restrict__ f = (const float4*)gsrc;
    for (int r = wid; r < BM; r += 8) {
        int node = m0 + r;
        if (node >= NN) break;
        int s = g_off[node], e = g_off[node + 1];
        float4 acc = make_float4(0.f, 0.f, 0.f, 0.f);
        int k = s;
        for (; k + 8 <= e; k += 8) {
            int c[8];
            #pragma unroll
            for (int j = 0; j < 8; j++) c[j] = __ldg(&g_col[k + j]);
            float4 v[8];
            #pragma unroll
            for (int j = 0; j < 8; j++) v[j] = __ldg(&f[(size_t)c[j] * 32 + lane]);
            acc.x += ((v[0].x + v[1].x) + (v[2].x + v[3].x)) + ((v[4].x + v[5].x) + (v[6].x + v[7].x));
            acc.y += ((v[0].y + v[1].y) + (v[2].y + v[3].y)) + ((v[4].y + v[5].y) + (v[6].y + v[7].y));
            acc.z += ((v[0].z + v[1].z) + (v[2].z + v[3].z)) + ((v[4].z + v[5].z) + (v[6].z + v[7].z));
            acc.w += ((v[0].w + v[1].w) + (v[2].w + v[3].w)) + ((v[4].w + v[5].w) + (v[6].w + v[7].w));
        }
        for (; k < e; k++) {
            float4 v = __ldg(&f[(size_t)__ldg(&g_col[k]) * 32 + lane]);
            acc.x += v.x; acc.y += v.y; acc.z += v.z; acc.w += v.w;
        }
        float inv = 1.f / fmaxf((float)(e - s), 1.f);
        ((float4*)g_mean)[(size_t)node * 32 + lane] =
            make_float4(acc.x * inv, acc.y * inv, acc.z * inv, acc.w * inv);
    }
}

// CFG=0: mean(x) -> g_h = relu([g_mean | x] @ [W1l;W1r] + b1l)
// CFG=1: mean(g_h) -> g_emb = [g_mean | g_h] @ [W2l;W2r] + b2l (-> g_emb + out),
//        then fused decoder + BCE loss
template <int CFG>
__global__ void __launch_bounds__(256, 2)
k_gemm(const float* __restrict__ xparam, const float* __restrict__ bias,
       float* __restrict__ out, int lead) {
    __shared__ __nv_bfloat16 As[2][BM * ALD];
    __shared__ __align__(16) __nv_bfloat16 Bs[2][32 * BLD];

    int tid = threadIdx.x;
    int wid = tid >> 5;
    int lane = tid & 31;
    int warp_m = wid & 3;
    int warp_n = wid >> 2;
    int m0 = blockIdx.x * BM;

    // phase A: aggregate mean for this block's rows
    mean_phase((CFG == 0) ? xparam : (const float*)g_h, m0, wid, lane);
    __syncthreads();   // mean writes visible block-wide

    AccFrag acc[4];
    #pragma unroll
    for (int nt = 0; nt < 4; nt++) wmma::fill_fragment(acc[nt], 0.f);

    if (CFG == 0)
        gemm_pipeline(g_mean, 0, xparam, 1, 2, m0, As, Bs, acc, tid, warp_m, warp_n);
    else
        gemm_pipeline(g_mean, 2, g_h, 3, 2, m0, As, Bs, acc, tid, warp_m, warp_n);

    float* buf = (float*)&Bs[0][0];
    #pragma unroll
    for (int pph = 0; pph < 2; pph++) {
        if ((warp_m >> 1) == pph) {
            int lr = (warp_m & 1) * 16;
            #pragma unroll
            for (int nt = 0; nt < 4; nt++)
                wmma::store_matrix_sync(&buf[lr * BLD + warp_n * 64 + nt * 16],
                                        acc[nt], BLD, wmma::mem_row_major);
        }
        __syncthreads();
        #pragma unroll
        for (int it = 0; it < 16; it++) {
            int id = tid + it * 256;
            int r = id >> 7, n = id & 127;
            int gm = m0 + pph * 32 + r;
            if (gm < NN) {
                float v = buf[r * BLD + n] + bias[n];
                if (CFG == 0) {
                    g_h[(size_t)gm * DD + n] = fmaxf(v, 0.f);
                } else {
                    g_emb[(size_t)gm * DD + n] = v;
                    if (lead >= 0) out[lead + (size_t)gm * DD + n] = v;
                }
            }
        }
        __syncthreads();
    }

    if (CFG == 1) {
        #pragma unroll
        for (int nt = 0; nt < 4; nt++) wmma::fill_fragment(acc[nt], 0.f);
        gemm_pipeline(g_emb, 4, g_emb, 4, 1, m0, As, Bs, acc, tid, warp_m, warp_n);

        float lp = 0.f, ln = 0.f;
        #pragma unroll
        for (int pph = 0; pph < 2; pph++) {
            if ((warp_m >> 1) == pph) {
                int lr = (warp_m & 1) * 16;
                #pragma unroll
                for (int nt = 0; nt < 4; nt++)
                    wmma::store_matrix_sync(&buf[lr * BLD + warp_n * 64 + nt * 16],
                                            acc[nt], BLD, wmma::mem_row_major);
            }
            __syncthreads();
            #pragma unroll
            for (int it = 0; it < 16; it++) {
                int id = tid + it * 256;
                int r = id >> 7, n = id & 127;
                int gm = m0 + pph * 32 + r;
                if (gm < NN) {
                    float v = buf[r * BLD + n];
                    bool pos = g_yb[gm] != 0;
                    float t2 = pos ? -v : v;
                    float sp = fmaxf(t2, 0.f) + log1pf(expf(-fabsf(t2)));
                    if (pos) lp += sp; else ln += sp;
                }
            }
            __syncthreads();
        }
        #pragma unroll
        for (int o = 16; o; o >>= 1) {
            lp += __shfl_down_sync(0xffffffffu, lp, o);
            ln += __shfl_down_sync(0xffffffffu, ln, o);
        }
        if ((tid & 31) == 0) {
            atomicAdd(&g_lp, lp);
            atomicAdd(&g_ln, ln);
        }
    }
}

// ---------------- finalize loss (restores accumulators to zero) ----------------
__global__ void k_final(float* __restrict__ out, int out_size) {
    float npos = (float)g_npos;
    float nneg = (float)(NN - g_npos);
    float l2 = g_lp / (fmaxf(npos, 1.f) * (float)DD);
    float l1 = g_ln / (fmaxf(nneg, 1.f) * (float)DD);
    float loss = l1 + l2;
    int lead = out_size - OUT_ELEMS;
    if (lead > 0) {
        for (int i = 0; i < lead && i < 16; i++) out[i] = loss;
    } else if (out_size > 0) {
        out[0] = loss;
    }
    g_lp = 0.f; g_ln = 0.f; g_npos = 0;
}

__global__ void k_copy(float* __restrict__ out, int out_size) {
    int i = blockIdx.x * blockDim.x + threadIdx.x;
    if (i < out_size && i < OUT_ELEMS) out[i] = g_emb[i];
}

// ---------------- launch ----------------
extern "C" void kernel_launch(void* const* d_in, const int* in_sizes, int n_in,
                              void* d_out, int out_size) {
    const float* x = nullptr;
    const void*  edge = nullptr;
    const void*  yv = nullptr;
    const float* Ws[5] = {nullptr, nullptr, nullptr, nullptr, nullptr};
    const float* bs[2] = {nullptr, nullptr};
    int wi = 0, bi = 0;
    for (int i = 0; i < n_in; i++) {
        int sz = in_sizes[i];
        if (sz == NN * DD && !x) x = (const float*)d_in[i];
        else if (sz == 2 * NE && !edge) edge = d_in[i];
        else if (sz == NN && !yv) yv = d_in[i];
        else if (sz == DD * DD && wi < 5) Ws[wi++] = (const float*)d_in[i];
        else if (sz == DD && bi < 2) bs[bi++] = (const float*)d_in[i];
    }
    const float* b1l = bs[0];
    const float* b2l = bs[1];
    float* out = (float*)d_out;
    int lead = out_size - OUT_ELEMS;

    k_prep <<<EDGE_BLOCKS, 256>>>(yv, edge, Ws[0], Ws[1], Ws[2], Ws[3], Ws[4]);
    k_scan <<<SCAN_B, 256>>>();
    k_fill <<<EDGE_BLOCKS, 256>>>(edge);

    // layer 1 (fused mean + GEMM) — 4th launch, profiled
    k_gemm<0><<<GEMM_BLOCKS, 256>>>(x, b1l, out, lead);

    // layer 2 (fused mean + GEMM + decoder + loss)
    k_gemm<1><<<GEMM_BLOCKS, 256>>>(nullptr, b2l, out, lead);

    k_final<<<1, 1>>>(out, out_size);
    if (lead < 0) k_copy<<<(OUT_ELEMS + 255) / 256, 256>>>(out, out_size);
}

// round 10
// speedup vs baseline: 1.1664x; 1.1664x over previous
#include <cuda_runtime.h>
#include <cuda_bf16.h>
#include <mma.h>
#include <math.h>
#include <stdint.h>

using namespace nvcuda;

#define NN 50000
#define NE 800000
#define DD 128
#define OUT_ELEMS (NN * DD)
#define BM 128
#define GEMM_BLOCKS ((NN + BM - 1) / BM)
#define SCAN_B ((NN + 255) / 256)
#define EPT 4
#define EDGE_BLOCKS ((NE / EPT + 255) / 256)
#define ALD 40
#define BLD 136
#define AS_BYTES (2 * 2 * 128 * ALD * 2)            // 40960
#define BS_BYTES (2 * 2 * 32 * BLD * 2)             // 34816
#define SMEM_DYN (AS_BYTES + BS_BYTES)              // 75776

// ---------------- device scratch (zero at load; every call restores zeros) --------
__device__ __align__(16) float g_mean[NN * DD];
__device__ __align__(16) float g_h[NN * DD];
__device__ __align__(16) float g_emb[NN * DD];
__device__ int   g_deg[NN];
__device__ int   g_off[NN + 1];
__device__ int   g_cur[NN];
__device__ int   g_col[NE];
__device__ unsigned char g_yb[NN];
__device__ float g_lp;
__device__ float g_ln;
__device__ int   g_npos;
__device__ unsigned long long g_lb[SCAN_B];
__device__ __align__(16) unsigned short g_Bimg[5][2][DD * DD];

// ---------------- per-block dtype detection ----------------
__device__ __forceinline__ int detect_e64(const void* edge) {
    __shared__ int s64;
    if (threadIdx.x == 0) s64 = 1;
    __syncthreads();
    if (threadIdx.x < 256) {
        long long v = ((const long long*)edge)[threadIdx.x];
        if (v < 0 || v >= NN) atomicAnd(&s64, 0);
    }
    __syncthreads();
    return s64;
}

__device__ __forceinline__ int edge_at(const void* edge, int idx, int e64) {
    if (e64) return (int)((const long long*)edge)[idx];
    return ((const int*)edge)[idx];
}

// ---------------- k_prep ----------------
__global__ void k_prep(const void* __restrict__ yv, const void* __restrict__ edge,
                       const float* __restrict__ W0, const float* __restrict__ W1,
                       const float* __restrict__ W2, const float* __restrict__ W3,
                       const float* __restrict__ W4) {
    __shared__ int s32;
    if (threadIdx.x == 0) s32 = 1;
    int e64 = detect_e64(edge);
    if (threadIdx.x < 64) {
        unsigned int w = ((const unsigned int*)yv)[threadIdx.x];
        if (w > 1u) atomicAnd(&s32, 0);
    }
    __syncthreads();
    int y32 = s32;

    int i = blockIdx.x * blockDim.x + threadIdx.x;
    int v = 0;
    if (i < NN) {
        if (y32) v = (((const int*)yv)[i] != 0) ? 1 : 0;
        else     v = (((const unsigned char*)yv)[i] != 0) ? 1 : 0;
        g_yb[i] = (unsigned char)v;
    }
    #pragma unroll
    for (int o = 16; o; o >>= 1) v += __shfl_down_sync(0xffffffffu, v, o);
    if ((threadIdx.x & 31) == 0 && v) atomicAdd(&g_npos, v);

    if (i < 5 * DD * DD) {
        int w = i / (DD * DD);
        int r = i % (DD * DD);
        const float* Wm = (w == 0) ? W0 : (w == 1) ? W1 : (w == 2) ? W2 : (w == 3) ? W3 : W4;
        float val = Wm[r];
        __nv_bfloat16 hi = __float2bfloat16(val);
        g_Bimg[w][0][r] = __bfloat16_as_ushort(hi);
        g_Bimg[w][1][r] = __bfloat16_as_ushort(__float2bfloat16(val - __bfloat162float(hi)));
    }

    int base = i * EPT;
    int d[EPT];
    #pragma unroll
    for (int j = 0; j < EPT; j++)
        d[j] = (base + j < NE) ? edge_at(edge, NE + base + j, e64) : -1;
    #pragma unroll
    for (int j = 0; j < EPT; j++)
        if (d[j] >= 0 && d[j] < NN) atomicAdd(&g_deg[d[j]], 1);
}

// ---------------- decoupled-lookback scan ----------------
__global__ void k_scan() {
    __shared__ int sh[256];
    __shared__ int s_ex;
    int b = blockIdx.x, t = threadIdx.x;
    int i = b * 256 + t;
    int v = (i < NN) ? g_deg[i] : 0;
    sh[t] = v;
    __syncthreads();
    for (int o = 1; o < 256; o <<= 1) {
        int add = (t >= o) ? sh[t - o] : 0;
        __syncthreads();
        sh[t] += add;
        __syncthreads();
    }
    int T = sh[255];
    if (t == 0) {
        if (b == 0) {
            atomicExch(&g_lb[0], (2ULL << 32) | (unsigned)T);
            s_ex = 0;
        } else {
            atomicExch(&g_lb[b], (1ULL << 32) | (unsigned)T);
            int ex = 0;
            for (int j = b - 1; j >= 0;) {
                unsigned long long w;
                do { w = atomicAdd(&g_lb[j], 0ULL); } while ((w >> 32) == 0ULL);
                if ((w >> 32) == 2ULL) { ex += (int)(unsigned)w; break; }
                ex += (int)(unsigned)w;
                j--;
            }
            atomicExch(&g_lb[b], (2ULL << 32) | (unsigned)(ex + T));
            s_ex = ex;
        }
    }
    __syncthreads();
    int ex = s_ex;
    if (i < NN) {
        int off = ex + sh[t] - v;
        g_off[i] = off;
        g_cur[i] = off;
        g_deg[i] = 0;
    }
    if (b == SCAN_B - 1 && t == 0) g_off[NN] = ex + T;
}

// ---------------- CSR fill ----------------
__global__ void k_fill(const void* __restrict__ edge) {
    int e64 = detect_e64(edge);
    int i = blockIdx.x * blockDim.x + threadIdx.x;
    if (i < SCAN_B) g_lb[i] = 0ULL;
    int base = i * EPT;
    int s[EPT], d[EPT];
    #pragma unroll
    for (int j = 0; j < EPT; j++) {
        if (base + j < NE) {
            d[j] = edge_at(edge, NE + base + j, e64);
            s[j] = edge_at(edge, base + j, e64);
        } else { d[j] = -1; s[j] = 0; }
    }
    #pragma unroll
    for (int j = 0; j < EPT; j++) {
        if (d[j] >= 0 && d[j] < NN && s[j] >= 0 && s[j] < NN) {
            int p = atomicAdd(&g_cur[d[j]], 1);
            g_col[p] = s[j];
        }
    }
}

// ---------------- mean aggregation: 1 warp per node (standalone, occ-friendly) ----
template <int SRC>
__global__ void k_mean(const float* __restrict__ feat) {
    int node = blockIdx.x * 8 + (threadIdx.x >> 5);
    int lane = threadIdx.x & 31;
    if (node >= NN) return;
    const float4* __restrict__ f = (const float4*)((SRC == 0) ? feat : (const float*)g_h);
    int s = g_off[node], e = g_off[node + 1];
    float4 acc = make_float4(0.f, 0.f, 0.f, 0.f);
    int k = s;
    for (; k + 8 <= e; k += 8) {
        int c[8];
        #pragma unroll
        for (int j = 0; j < 8; j++) c[j] = __ldg(&g_col[k + j]);
        float4 v[8];
        #pragma unroll
        for (int j = 0; j < 8; j++) v[j] = __ldg(&f[(size_t)c[j] * 32 + lane]);
        acc.x += ((v[0].x + v[1].x) + (v[2].x + v[3].x)) + ((v[4].x + v[5].x) + (v[6].x + v[7].x));
        acc.y += ((v[0].y + v[1].y) + (v[2].y + v[3].y)) + ((v[4].y + v[5].y) + (v[6].y + v[7].y));
        acc.z += ((v[0].z + v[1].z) + (v[2].z + v[3].z)) + ((v[4].z + v[5].z) + (v[6].z + v[7].z));
        acc.w += ((v[0].w + v[1].w) + (v[2].w + v[3].w)) + ((v[4].w + v[5].w) + (v[6].w + v[7].w));
    }
    for (; k < e; k++) {
        float4 v = __ldg(&f[(size_t)__ldg(&g_col[k]) * 32 + lane]);
        acc.x += v.x; acc.y += v.y; acc.z += v.z; acc.w += v.w;
    }
    float inv = 1.f / fmaxf((float)(e - s), 1.f);
    ((float4*)g_mean)[(size_t)node * 32 + lane] =
        make_float4(acc.x * inv, acc.y * inv, acc.z * inv, acc.w * inv);
}

// ---------------- double-buffered WMMA bf16x3 GEMM, BM=128, 512 threads -----------
typedef wmma::fragment<wmma::accumulator, 16, 16, 16, float> AccFrag;

struct Pref {
    float4 a[2];
    uint4  b[2];
};

__device__ __forceinline__ __nv_bfloat16* as_ptr(char* sdyn, int buf, int hl) {
    return (__nv_bfloat16*)sdyn + (size_t)(buf * 2 + hl) * 128 * ALD;
}
__device__ __forceinline__ __nv_bfloat16* bs_ptr(char* sdyn, int buf, int hl) {
    return (__nv_bfloat16*)(sdyn + AS_BYTES) + (size_t)(buf * 2 + hl) * 32 * BLD;
}

__device__ __forceinline__ void pf_load(Pref& p, const float* __restrict__ Asrc,
                                        int wsel, int c, int m0, int tid) {
    #pragma unroll
    for (int it = 0; it < 2; it++) {
        int id = tid + it * 512;              // 1024 float4 total (128 rows x 8)
        int row = id >> 3, q = id & 7;
        int gm = m0 + row;
        p.a[it] = (gm < NN) ? *(const float4*)&Asrc[(size_t)gm * DD + c * 32 + q * 4]
                            : make_float4(0.f, 0.f, 0.f, 0.f);
    }
    #pragma unroll
    for (int it = 0; it < 2; it++) {          // hl = it; 512 uint4 per image
        int k = tid >> 4, c16 = tid & 15;
        p.b[it] = ((const uint4*)&g_Bimg[wsel][it][(c * 32 + k) * DD])[c16];
    }
}

__device__ __forceinline__ void pf_store(const Pref& p, char* sdyn, int buf, int tid) {
    __nv_bfloat16* Ah = as_ptr(sdyn, buf, 0);
    __nv_bfloat16* Al = as_ptr(sdyn, buf, 1);
    #pragma unroll
    for (int it = 0; it < 2; it++) {
        int id = tid + it * 512;
        int row = id >> 3, q = id & 7;
        float vv[4] = {p.a[it].x, p.a[it].y, p.a[it].z, p.a[it].w};
        #pragma unroll
        for (int j = 0; j < 4; j++) {
            __nv_bfloat16 hi = __float2bfloat16(vv[j]);
            Ah[row * ALD + q * 4 + j] = hi;
            Al[row * ALD + q * 4 + j] = __float2bfloat16(vv[j] - __bfloat162float(hi));
        }
    }
    #pragma unroll
    for (int it = 0; it < 2; it++) {
        __nv_bfloat16* B = bs_ptr(sdyn, buf, it);
        int k = tid >> 4, c16 = tid & 15;
        ((uint4*)&B[k * BLD])[c16] = p.b[it];
    }
}

__device__ __forceinline__ void mma_chunk(char* sdyn, int buf,
                                          AccFrag (&acc)[2][2], int warp_m, int warp_n) {
    __nv_bfloat16* Ah = as_ptr(sdyn, buf, 0);
    __nv_bfloat16* Al = as_ptr(sdyn, buf, 1);
    __nv_bfloat16* Bh = bs_ptr(sdyn, buf, 0);
    __nv_bfloat16* Bl = bs_ptr(sdyn, buf, 1);
    #pragma unroll
    for (int ks = 0; ks < 2; ks++) {
        wmma::fragment<wmma::matrix_a, 16, 16, 16, __nv_bfloat16, wmma::row_major> a_hi[2], a_lo[2];
        #pragma unroll
        for (int mt = 0; mt < 2; mt++) {
            int mr = (warp_m * 32 + mt * 16) * ALD + ks * 16;
            wmma::load_matrix_sync(a_hi[mt], &Ah[mr], ALD);
            wmma::load_matrix_sync(a_lo[mt], &Al[mr], ALD);
        }
        #pragma unroll
        for (int nt = 0; nt < 2; nt++) {
            int nb = warp_n * 32 + nt * 16;
            wmma::fragment<wmma::matrix_b, 16, 16, 16, __nv_bfloat16, wmma::row_major> b_hi, b_lo;
            wmma::load_matrix_sync(b_hi, &Bh[ks * 16 * BLD + nb], BLD);
            wmma::load_matrix_sync(b_lo, &Bl[ks * 16 * BLD + nb], BLD);
            #pragma unroll
            for (int mt = 0; mt < 2; mt++) {
                wmma::mma_sync(acc[mt][nt], a_hi[mt], b_hi, acc[mt][nt]);
                wmma::mma_sync(acc[mt][nt], a_hi[mt], b_lo, acc[mt][nt]);
                wmma::mma_sync(acc[mt][nt], a_lo[mt], b_hi, acc[mt][nt]);
            }
        }
    }
}

__device__ __forceinline__ void gemm_pipeline(
    char* sdyn,
    const float* __restrict__ src0, int wsel0,
    const float* __restrict__ src1, int wsel1, int nsrc,
    int m0, AccFrag (&acc)[2][2], int tid, int warp_m, int warp_n) {
    Pref p;
    pf_load(p, src0, wsel0, 0, m0, tid);
    int T = nsrc * 4;
    for (int t = 0; t < T; t++) {
        int buf = t & 1;
        pf_store(p, sdyn, buf, tid);
        __syncthreads();
        if (t + 1 < T) {
            const float* nptr = ((t + 1) >> 2) ? src1 : src0;
            int nwsel = ((t + 1) >> 2) ? wsel1 : wsel0;
            pf_load(p, nptr, nwsel, (t + 1) & 3, m0, tid);
        }
        mma_chunk(sdyn, buf, acc, warp_m, warp_n);
    }
    __syncthreads();
}

// CFG=0: g_h   = relu([g_mean | x] @ [W1l;W1r] + b1l)
// CFG=1: g_emb = [g_mean | g_h] @ [W2l;W2r] + b2l (-> g_emb + out), then decoder+loss
template <int CFG>
__global__ void __launch_bounds__(512, 1)
k_gemm(const float* __restrict__ xparam, const float* __restrict__ bias,
       float* __restrict__ out, int lead) {
    extern __shared__ char sdyn[];
    int tid = threadIdx.x;
    int wid = tid >> 5;
    int warp_m = wid & 3;       // 4 M-groups x 32 rows
    int warp_n = wid >> 2;      // 4 N-groups x 32 cols
    int m0 = blockIdx.x * BM;

    AccFrag acc[2][2];
    #pragma unroll
    for (int mt = 0; mt < 2; mt++)
        #pragma unroll
        for (int nt = 0; nt < 2; nt++) wmma::fill_fragment(acc[mt][nt], 0.f);

    if (CFG == 0)
        gemm_pipeline(sdyn, g_mean, 0, xparam, 1, 2, m0, acc, tid, warp_m, warp_n);
    else
        gemm_pipeline(sdyn, g_mean, 2, g_h, 3, 2, m0, acc, tid, warp_m, warp_n);

    // ---------------- epilogue: 4 phases of 32 rows via smem buffer -------------
    float* buf = (float*)sdyn;   // 32 x BLD floats = 17.4KB
    #pragma unroll
    for (int ph = 0; ph < 4; ph++) {
        if (warp_m == ph) {
            #pragma unroll
            for (int mt = 0; mt < 2; mt++)
                #pragma unroll
                for (int nt = 0; nt < 2; nt++)
                    wmma::store_matrix_sync(&buf[(mt * 16) * BLD + warp_n * 32 + nt * 16],
                                            acc[mt][nt], BLD, wmma::mem_row_major);
        }
        __syncthreads();
        #pragma unroll
        for (int it = 0; it < 8; it++) {
            int id = tid + it * 512;
            int r = id >> 7, n = id & 127;
            int gm = m0 + ph * 32 + r;
            if (gm < NN) {
                float v = buf[r * BLD + n] + bias[n];
                if (CFG == 0) {
                    g_h[(size_t)gm * DD + n] = fmaxf(v, 0.f);
                } else {
                    g_emb[(size_t)gm * DD + n] = v;
                    if (lead >= 0) out[lead + (size_t)gm * DD + n] = v;
                }
            }
        }
        __syncthreads();
    }

    // ---------------- fused decoder + BCE loss (CFG==1) -------------------------
    if (CFG == 1) {
        #pragma unroll
        for (int mt = 0; mt < 2; mt++)
            #pragma unroll
            for (int nt = 0; nt < 2; nt++) wmma::fill_fragment(acc[mt][nt], 0.f);
        gemm_pipeline(sdyn, g_emb, 4, g_emb, 4, 1, m0, acc, tid, warp_m, warp_n);

        float lp = 0.f, ln = 0.f;
        #pragma unroll
        for (int ph = 0; ph < 4; ph++) {
            if (warp_m == ph) {
                #pragma unroll
                for (int mt = 0; mt < 2; mt++)
                    #pragma unroll
                    for (int nt = 0; nt < 2; nt++)
                        wmma::store_matrix_sync(&buf[(mt * 16) * BLD + warp_n * 32 + nt * 16],
                                                acc[mt][nt], BLD, wmma::mem_row_major);
            }
            __syncthreads();
            #pragma unroll
            for (int it = 0; it < 8; it++) {
                int id = tid + it * 512;
                int r = id >> 7, n = id & 127;
                int gm = m0 + ph * 32 + r;
                if (gm < NN) {
                    float v = buf[r * BLD + n];
                    bool pos = g_yb[gm] != 0;
                    float t2 = pos ? -v : v;
                    float sp = fmaxf(t2, 0.f) + log1pf(expf(-fabsf(t2)));
                    if (pos) lp += sp; else ln += sp;
                }
            }
            __syncthreads();
        }
        #pragma unroll
        for (int o = 16; o; o >>= 1) {
            lp += __shfl_down_sync(0xffffffffu, lp, o);
            ln += __shfl_down_sync(0xffffffffu, ln, o);
        }
        if ((tid & 31) == 0) {
            atomicAdd(&g_lp, lp);
            atomicAdd(&g_ln, ln);
        }
    }
}

// ---------------- finalize loss ----------------
__global__ void k_final(float* __restrict__ out, int out_size) {
    float npos = (float)g_npos;
    float nneg = (float)(NN - g_npos);
    float l2 = g_lp / (fmaxf(npos, 1.f) * (float)DD);
    float l1 = g_ln / (fmaxf(nneg, 1.f) * (float)DD);
    float loss = l1 + l2;
    int lead = out_size - OUT_ELEMS;
    if (lead > 0) {
        for (int i = 0; i < lead && i < 16; i++) out[i] = loss;
    } else if (out_size > 0) {
        out[0] = loss;
    }
    g_lp = 0.f; g_ln = 0.f; g_npos = 0;
}

__global__ void k_copy(float* __restrict__ out, int out_size) {
    int i = blockIdx.x * blockDim.x + threadIdx.x;
    if (i < out_size && i < OUT_ELEMS) out[i] = g_emb[i];
}

// ---------------- launch ----------------
extern "C" void kernel_launch(void* const* d_in, const int* in_sizes, int n_in,
                              void* d_out, int out_size) {
    const float* x = nullptr;
    const void*  edge = nullptr;
    const void*  yv = nullptr;
    const float* Ws[5] = {nullptr, nullptr, nullptr, nullptr, nullptr};
    const float* bs[2] = {nullptr, nullptr};
    int wi = 0, bi = 0;
    for (int i = 0; i < n_in; i++) {
        int sz = in_sizes[i];
        if (sz == NN * DD && !x) x = (const float*)d_in[i];
        else if (sz == 2 * NE && !edge) edge = d_in[i];
        else if (sz == NN && !yv) yv = d_in[i];
        else if (sz == DD * DD && wi < 5) Ws[wi++] = (const float*)d_in[i];
        else if (sz == DD && bi < 2) bs[bi++] = (const float*)d_in[i];
    }
    const float* b1l = bs[0];
    const float* b2l = bs[1];
    float* out = (float*)d_out;
    int lead = out_size - OUT_ELEMS;

    cudaFuncSetAttribute(k_gemm<0>, cudaFuncAttributeMaxDynamicSharedMemorySize, SMEM_DYN);
    cudaFuncSetAttribute(k_gemm<1>, cudaFuncAttributeMaxDynamicSharedMemorySize, SMEM_DYN);

    k_prep <<<EDGE_BLOCKS, 256>>>(yv, edge, Ws[0], Ws[1], Ws[2], Ws[3], Ws[4]);
    k_scan <<<SCAN_B, 256>>>();
    k_fill <<<EDGE_BLOCKS, 256>>>(edge);

    // layer 1
    k_mean<0><<<(NN + 7) / 8, 256>>>(x);
    k_gemm<0><<<GEMM_BLOCKS, 512, SMEM_DYN>>>(x, b1l, out, lead);

    // layer 2 + fused decoder + loss
    k_mean<1><<<(NN + 7) / 8, 256>>>(nullptr);
    k_gemm<1><<<GEMM_BLOCKS, 512, SMEM_DYN>>>(nullptr, b2l, out, lead);

    k_final<<<1, 1>>>(out, out_size);
    if (lead < 0) k_copy<<<(OUT_ELEMS + 255) / 256, 256>>>(out, out_size);
}

// round 11
// speedup vs baseline: 1.1853x; 1.0162x over previous
#include <cuda_runtime.h>
#include <cuda_bf16.h>
#include <mma.h>
#include <math.h>
#include <stdint.h>

using namespace nvcuda;

#define NN 50000
#define NE 800000
#define DD 128
#define OUT_ELEMS (NN * DD)
#define BM 128
#define GEMM_BLOCKS ((NN + BM - 1) / BM)
#define SCAN_B ((NN + 255) / 256)
#define EPT 4
#define EDGE_BLOCKS ((NE / EPT + 255) / 256)
#define ALD 40
#define BLD 136
#define AS_BYTES (2 * 2 * 128 * ALD * 2)            // 40960
#define BS_BYTES (2 * 2 * 32 * BLD * 2)             // 34816
#define EMB_BYTES (2 * 128 * BLD * 2)               // 69632 (hi+lo, 128 x BLD bf16)
#define SMEM_G0 (AS_BYTES + BS_BYTES)               // 75776
#define SMEM_G1 (AS_BYTES + BS_BYTES + EMB_BYTES)   // 145408

// ---------------- device scratch (zero at load; every call restores zeros) --------
__device__ __align__(16) float g_mean[NN * DD];
__device__ __align__(16) float g_h[NN * DD];
__device__ __align__(16) float g_emb[NN * DD];     // only used when lead < 0
__device__ int   g_deg[NN];
__device__ int   g_off[NN + 1];
__device__ int   g_cur[NN];
__device__ int   g_col[NE];
__device__ unsigned char g_yb[NN];
__device__ float g_lp;
__device__ float g_ln;
__device__ int   g_npos;
__device__ int   g_done;
__device__ unsigned long long g_lb[SCAN_B];
__device__ __align__(16) unsigned short g_Bimg[5][2][DD * DD];

// ---------------- per-block dtype detection ----------------
__device__ __forceinline__ int detect_e64(const void* edge) {
    __shared__ int s64;
    if (threadIdx.x == 0) s64 = 1;
    __syncthreads();
    if (threadIdx.x < 256) {
        long long v = ((const long long*)edge)[threadIdx.x];
        if (v < 0 || v >= NN) atomicAnd(&s64, 0);
    }
    __syncthreads();
    return s64;
}

__device__ __forceinline__ int edge_at(const void* edge, int idx, int e64) {
    if (e64) return (int)((const long long*)edge)[idx];
    return ((const int*)edge)[idx];
}

// ---------------- k_prep ----------------
__global__ void k_prep(const void* __restrict__ yv, const void* __restrict__ edge,
                       const float* __restrict__ W0, const float* __restrict__ W1,
                       const float* __restrict__ W2, const float* __restrict__ W3,
                       const float* __restrict__ W4) {
    __shared__ int s32;
    if (threadIdx.x == 0) s32 = 1;
    int e64 = detect_e64(edge);
    if (threadIdx.x < 64) {
        unsigned int w = ((const unsigned int*)yv)[threadIdx.x];
        if (w > 1u) atomicAnd(&s32, 0);
    }
    __syncthreads();
    int y32 = s32;

    int i = blockIdx.x * blockDim.x + threadIdx.x;
    int v = 0;
    if (i < NN) {
        if (y32) v = (((const int*)yv)[i] != 0) ? 1 : 0;
        else     v = (((const unsigned char*)yv)[i] != 0) ? 1 : 0;
        g_yb[i] = (unsigned char)v;
    }
    #pragma unroll
    for (int o = 16; o; o >>= 1) v += __shfl_down_sync(0xffffffffu, v, o);
    if ((threadIdx.x & 31) == 0 && v) atomicAdd(&g_npos, v);

    if (i < 5 * DD * DD) {
        int w = i / (DD * DD);
        int r = i % (DD * DD);
        const float* Wm = (w == 0) ? W0 : (w == 1) ? W1 : (w == 2) ? W2 : (w == 3) ? W3 : W4;
        float val = Wm[r];
        __nv_bfloat16 hi = __float2bfloat16(val);
        g_Bimg[w][0][r] = __bfloat16_as_ushort(hi);
        g_Bimg[w][1][r] = __bfloat16_as_ushort(__float2bfloat16(val - __bfloat162float(hi)));
    }

    int base = i * EPT;
    int d[EPT];
    #pragma unroll
    for (int j = 0; j < EPT; j++)
        d[j] = (base + j < NE) ? edge_at(edge, NE + base + j, e64) : -1;
    #pragma unroll
    for (int j = 0; j < EPT; j++)
        if (d[j] >= 0 && d[j] < NN) atomicAdd(&g_deg[d[j]], 1);
}

// ---------------- decoupled-lookback scan ----------------
__global__ void k_scan() {
    __shared__ int sh[256];
    __shared__ int s_ex;
    int b = blockIdx.x, t = threadIdx.x;
    int i = b * 256 + t;
    int v = (i < NN) ? g_deg[i] : 0;
    sh[t] = v;
    __syncthreads();
    for (int o = 1; o < 256; o <<= 1) {
        int add = (t >= o) ? sh[t - o] : 0;
        __syncthreads();
        sh[t] += add;
        __syncthreads();
    }
    int T = sh[255];
    if (t == 0) {
        if (b == 0) {
            atomicExch(&g_lb[0], (2ULL << 32) | (unsigned)T);
            s_ex = 0;
        } else {
            atomicExch(&g_lb[b], (1ULL << 32) | (unsigned)T);
            int ex = 0;
            for (int j = b - 1; j >= 0;) {
                unsigned long long w;
                do { w = atomicAdd(&g_lb[j], 0ULL); } while ((w >> 32) == 0ULL);
                if ((w >> 32) == 2ULL) { ex += (int)(unsigned)w; break; }
                ex += (int)(unsigned)w;
                j--;
            }
            atomicExch(&g_lb[b], (2ULL << 32) | (unsigned)(ex + T));
            s_ex = ex;
        }
    }
    __syncthreads();
    int ex = s_ex;
    if (i < NN) {
        int off = ex + sh[t] - v;
        g_off[i] = off;
        g_cur[i] = off;
        g_deg[i] = 0;
    }
    if (b == SCAN_B - 1 && t == 0) g_off[NN] = ex + T;
}

// ---------------- CSR fill ----------------
__global__ void k_fill(const void* __restrict__ edge) {
    int e64 = detect_e64(edge);
    int i = blockIdx.x * blockDim.x + threadIdx.x;
    if (i < SCAN_B) g_lb[i] = 0ULL;
    int base = i * EPT;
    int s[EPT], d[EPT];
    #pragma unroll
    for (int j = 0; j < EPT; j++) {
        if (base + j < NE) {
            d[j] = edge_at(edge, NE + base + j, e64);
            s[j] = edge_at(edge, base + j, e64);
        } else { d[j] = -1; s[j] = 0; }
    }
    #pragma unroll
    for (int j = 0; j < EPT; j++) {
        if (d[j] >= 0 && d[j] < NN && s[j] >= 0 && s[j] < NN) {
            int p = atomicAdd(&g_cur[d[j]], 1);
            g_col[p] = s[j];
        }
    }
}

// ---------------- mean aggregation: 1 warp per node ----------------
template <int SRC>
__global__ void k_mean(const float* __restrict__ feat) {
    int node = blockIdx.x * 8 + (threadIdx.x >> 5);
    int lane = threadIdx.x & 31;
    if (node >= NN) return;
    const float4* __restrict__ f = (const float4*)((SRC == 0) ? feat : (const float*)g_h);
    int s = g_off[node], e = g_off[node + 1];
    float4 acc = make_float4(0.f, 0.f, 0.f, 0.f);
    int k = s;
    for (; k + 8 <= e; k += 8) {
        int c[8];
        #pragma unroll
        for (int j = 0; j < 8; j++) c[j] = __ldg(&g_col[k + j]);
        float4 v[8];
        #pragma unroll
        for (int j = 0; j < 8; j++) v[j] = __ldg(&f[(size_t)c[j] * 32 + lane]);
        acc.x += ((v[0].x + v[1].x) + (v[2].x + v[3].x)) + ((v[4].x + v[5].x) + (v[6].x + v[7].x));
        acc.y += ((v[0].y + v[1].y) + (v[2].y + v[3].y)) + ((v[4].y + v[5].y) + (v[6].y + v[7].y));
        acc.z += ((v[0].z + v[1].z) + (v[2].z + v[3].z)) + ((v[4].z + v[5].z) + (v[6].z + v[7].z));
        acc.w += ((v[0].w + v[1].w) + (v[2].w + v[3].w)) + ((v[4].w + v[5].w) + (v[6].w + v[7].w));
    }
    for (; k < e; k++) {
        float4 v = __ldg(&f[(size_t)__ldg(&g_col[k]) * 32 + lane]);
        acc.x += v.x; acc.y += v.y; acc.z += v.z; acc.w += v.w;
    }
    float inv = 1.f / fmaxf((float)(e - s), 1.f);
    ((float4*)g_mean)[(size_t)node * 32 + lane] =
        make_float4(acc.x * inv, acc.y * inv, acc.z * inv, acc.w * inv);
}

// ---------------- double-buffered WMMA bf16x3 GEMM, BM=128, 512 threads -----------
typedef wmma::fragment<wmma::accumulator, 16, 16, 16, float> AccFrag;

struct Pref {
    float4 a[2];
    uint4  b[2];
};

__device__ __forceinline__ __nv_bfloat16* as_ptr(char* sdyn, int buf, int hl) {
    return (__nv_bfloat16*)sdyn + (size_t)(buf * 2 + hl) * 128 * ALD;
}
__device__ __forceinline__ __nv_bfloat16* bs_ptr(char* sdyn, int buf, int hl) {
    return (__nv_bfloat16*)(sdyn + AS_BYTES) + (size_t)(buf * 2 + hl) * 32 * BLD;
}
__device__ __forceinline__ __nv_bfloat16* emb_ptr(char* sdyn, int hl) {
    return (__nv_bfloat16*)(sdyn + AS_BYTES + BS_BYTES) + (size_t)hl * 128 * BLD;
}

__device__ __forceinline__ void pf_load(Pref& p, const float* __restrict__ Asrc,
                                        int wsel, int c, int m0, int tid) {
    #pragma unroll
    for (int it = 0; it < 2; it++) {
        int id = tid + it * 512;
        int row = id >> 3, q = id & 7;
        int gm = m0 + row;
        p.a[it] = (gm < NN) ? *(const float4*)&Asrc[(size_t)gm * DD + c * 32 + q * 4]
                            : make_float4(0.f, 0.f, 0.f, 0.f);
    }
    #pragma unroll
    for (int it = 0; it < 2; it++) {
        int k = tid >> 4, c16 = tid & 15;
        p.b[it] = ((const uint4*)&g_Bimg[wsel][it][(c * 32 + k) * DD])[c16];
    }
}

__device__ __forceinline__ void pf_store(const Pref& p, char* sdyn, int buf, int tid) {
    __nv_bfloat16* Ah = as_ptr(sdyn, buf, 0);
    __nv_bfloat16* Al = as_ptr(sdyn, buf, 1);
    #pragma unroll
    for (int it = 0; it < 2; it++) {
        int id = tid + it * 512;
        int row = id >> 3, q = id & 7;
        float vv[4] = {p.a[it].x, p.a[it].y, p.a[it].z, p.a[it].w};
        #pragma unroll
        for (int j = 0; j < 4; j++) {
            __nv_bfloat16 hi = __float2bfloat16(vv[j]);
            Ah[row * ALD + q * 4 + j] = hi;
            Al[row * ALD + q * 4 + j] = __float2bfloat16(vv[j] - __bfloat162float(hi));
        }
    }
    #pragma unroll
    for (int it = 0; it < 2; it++) {
        __nv_bfloat16* B = bs_ptr(sdyn, buf, it);
        int k = tid >> 4, c16 = tid & 15;
        ((uint4*)&B[k * BLD])[c16] = p.b[it];
    }
}

__device__ __forceinline__ void mma_chunk(char* sdyn, int buf,
                                          AccFrag (&acc)[2][2], int warp_m, int warp_n) {
    __nv_bfloat16* Ah = as_ptr(sdyn, buf, 0);
    __nv_bfloat16* Al = as_ptr(sdyn, buf, 1);
    __nv_bfloat16* Bh = bs_ptr(sdyn, buf, 0);
    __nv_bfloat16* Bl = bs_ptr(sdyn, buf, 1);
    #pragma unroll
    for (int ks = 0; ks < 2; ks++) {
        wmma::fragment<wmma::matrix_a, 16, 16, 16, __nv_bfloat16, wmma::row_major> a_hi[2], a_lo[2];
        #pragma unroll
        for (int mt = 0; mt < 2; mt++) {
            int mr = (warp_m * 32 + mt * 16) * ALD + ks * 16;
            wmma::load_matrix_sync(a_hi[mt], &Ah[mr], ALD);
            wmma::load_matrix_sync(a_lo[mt], &Al[mr], ALD);
        }
        #pragma unroll
        for (int nt = 0; nt < 2; nt++) {
            int nb = warp_n * 32 + nt * 16;
            wmma::fragment<wmma::matrix_b, 16, 16, 16, __nv_bfloat16, wmma::row_major> b_hi, b_lo;
            wmma::load_matrix_sync(b_hi, &Bh[ks * 16 * BLD + nb], BLD);
            wmma::load_matrix_sync(b_lo, &Bl[ks * 16 * BLD + nb], BLD);
            #pragma unroll
            for (int mt = 0; mt < 2; mt++) {
                wmma::mma_sync(acc[mt][nt], a_hi[mt], b_hi, acc[mt][nt]);
                wmma::mma_sync(acc[mt][nt], a_hi[mt], b_lo, acc[mt][nt]);
                wmma::mma_sync(acc[mt][nt], a_lo[mt], b_hi, acc[mt][nt]);
            }
        }
    }
}

// decoder mma: A frags straight from smem emb image, B from Bs buffer
__device__ __forceinline__ void mma_dec(char* sdyn, int buf, int c,
                                        AccFrag (&acc)[2][2], int warp_m, int warp_n) {
    __nv_bfloat16* Eh = emb_ptr(sdyn, 0);
    __nv_bfloat16* El = emb_ptr(sdyn, 1);
    __nv_bfloat16* Bh = bs_ptr(sdyn, buf, 0);
    __nv_bfloat16* Bl = bs_ptr(sdyn, buf, 1);
    #pragma unroll
    for (int ks = 0; ks < 2; ks++) {
        wmma::fragment<wmma::matrix_a, 16, 16, 16, __nv_bfloat16, wmma::row_major> a_hi[2], a_lo[2];
        #pragma unroll
        for (int mt = 0; mt < 2; mt++) {
            int mr = (warp_m * 32 + mt * 16) * BLD + c * 32 + ks * 16;
            wmma::load_matrix_sync(a_hi[mt], &Eh[mr], BLD);
            wmma::load_matrix_sync(a_lo[mt], &El[mr], BLD);
        }
        #pragma unroll
        for (int nt = 0; nt < 2; nt++) {
            int nb = warp_n * 32 + nt * 16;
            wmma::fragment<wmma::matrix_b, 16, 16, 16, __nv_bfloat16, wmma::row_major> b_hi, b_lo;
            wmma::load_matrix_sync(b_hi, &Bh[ks * 16 * BLD + nb], BLD);
            wmma::load_matrix_sync(b_lo, &Bl[ks * 16 * BLD + nb], BLD);
            #pragma unroll
            for (int mt = 0; mt < 2; mt++) {
                wmma::mma_sync(acc[mt][nt], a_hi[mt], b_hi, acc[mt][nt]);
                wmma::mma_sync(acc[mt][nt], a_hi[mt], b_lo, acc[mt][nt]);
                wmma::mma_sync(acc[mt][nt], a_lo[mt], b_hi, acc[mt][nt]);
            }
        }
    }
}

__device__ __forceinline__ void gemm_pipeline(
    char* sdyn,
    const float* __restrict__ src0, int wsel0,
    const float* __restrict__ src1, int wsel1,
    int m0, AccFrag (&acc)[2][2], int tid, int warp_m, int warp_n) {
    Pref p;
    pf_load(p, src0, wsel0, 0, m0, tid);
    const int T = 8;
    for (int t = 0; t < T; t++) {
        int buf = t & 1;
        pf_store(p, sdyn, buf, tid);
        __syncthreads();
        if (t + 1 < T) {
            const float* nptr = ((t + 1) >> 2) ? src1 : src0;
            int nwsel = ((t + 1) >> 2) ? wsel1 : wsel0;
            pf_load(p, nptr, nwsel, (t + 1) & 3, m0, tid);
        }
        mma_chunk(sdyn, buf, acc, warp_m, warp_n);
    }
    __syncthreads();
}

// CFG=0: g_h = relu([g_mean | x] @ [W1l;W1r] + b1l)
// CFG=1: emb = [g_mean | g_h] @ [W2l;W2r] + b2l -> out (and smem); decoder+loss+final
template <int CFG>
__global__ void __launch_bounds__(512, 1)
k_gemm(const float* __restrict__ xparam, const float* __restrict__ bias,
       float* __restrict__ out, int lead, int out_size) {
    extern __shared__ char sdyn[];
    int tid = threadIdx.x;
    int wid = tid >> 5;
    int warp_m = wid & 3;
    int warp_n = wid >> 2;
    int m0 = blockIdx.x * BM;

    AccFrag acc[2][2];
    #pragma unroll
    for (int mt = 0; mt < 2; mt++)
        #pragma unroll
        for (int nt = 0; nt < 2; nt++) wmma::fill_fragment(acc[mt][nt], 0.f);

    if (CFG == 0)
        gemm_pipeline(sdyn, g_mean, 0, xparam, 1, m0, acc, tid, warp_m, warp_n);
    else
        gemm_pipeline(sdyn, g_mean, 2, g_h, 3, m0, acc, tid, warp_m, warp_n);

    // ---------------- epilogue: bias (+relu); CFG1 also builds smem emb image ----
    float* buf = (float*)sdyn;   // 32 x BLD fp32, aliases As (pipeline done)
    __nv_bfloat16* Eh = emb_ptr(sdyn, 0);
    __nv_bfloat16* El = emb_ptr(sdyn, 1);
    #pragma unroll
    for (int ph = 0; ph < 4; ph++) {
        if (warp_m == ph) {
            #pragma unroll
            for (int mt = 0; mt < 2; mt++)
                #pragma unroll
                for (int nt = 0; nt < 2; nt++)
                    wmma::store_matrix_sync(&buf[(mt * 16) * BLD + warp_n * 32 + nt * 16],
                                            acc[mt][nt], BLD, wmma::mem_row_major);
        }
        __syncthreads();
        #pragma unroll
        for (int it = 0; it < 8; it++) {
            int id = tid + it * 512;
            int r = id >> 7, n = id & 127;
            int gm = m0 + ph * 32 + r;
            float v = buf[r * BLD + n] + bias[n];
            if (CFG == 0) {
                if (gm < NN) g_h[(size_t)gm * DD + n] = fmaxf(v, 0.f);
            } else {
                int lr = ph * 32 + r;
                __nv_bfloat16 hi = __float2bfloat16(v);
                Eh[lr * BLD + n] = hi;
                El[lr * BLD + n] = __float2bfloat16(v - __bfloat162float(hi));
                if (gm < NN) {
                    if (lead >= 0) out[lead + (size_t)gm * DD + n] = v;
                    else           g_emb[(size_t)gm * DD + n] = v;
                }
            }
        }
        __syncthreads();
    }

    // ---------------- fused decoder (A from smem) + BCE loss + final (CFG==1) ----
    if (CFG == 1) {
        #pragma unroll
        for (int mt = 0; mt < 2; mt++)
            #pragma unroll
            for (int nt = 0; nt < 2; nt++) wmma::fill_fragment(acc[mt][nt], 0.f);

        // B-only pipeline over 4 K-chunks of Wdec (wsel=4)
        uint4 pb[2];
        {
            int k = tid >> 4, c16 = tid & 15;
            pb[0] = ((const uint4*)&g_Bimg[4][0][k * DD])[c16];
            pb[1] = ((const uint4*)&g_Bimg[4][1][k * DD])[c16];
        }
        for (int t = 0; t < 4; t++) {
            int bf = t & 1;
            {
                int k = tid >> 4, c16 = tid & 15;
                ((uint4*)&bs_ptr(sdyn, bf, 0)[k * BLD])[c16] = pb[0];
                ((uint4*)&bs_ptr(sdyn, bf, 1)[k * BLD])[c16] = pb[1];
            }
            __syncthreads();
            if (t + 1 < 4) {
                int k = tid >> 4, c16 = tid & 15;
                pb[0] = ((const uint4*)&g_Bimg[4][0][((t + 1) * 32 + k) * DD])[c16];
                pb[1] = ((const uint4*)&g_Bimg[4][1][((t + 1) * 32 + k) * DD])[c16];
            }
            mma_dec(sdyn, bf, t, acc, warp_m, warp_n);
        }
        __syncthreads();

        float lp = 0.f, ln = 0.f;
        #pragma unroll
        for (int ph = 0; ph < 4; ph++) {
            if (warp_m == ph) {
                #pragma unroll
                for (int mt = 0; mt < 2; mt++)
                    #pragma unroll
                    for (int nt = 0; nt < 2; nt++)
                        wmma::store_matrix_sync(&buf[(mt * 16) * BLD + warp_n * 32 + nt * 16],
                                                acc[mt][nt], BLD, wmma::mem_row_major);
            }
            __syncthreads();
            #pragma unroll
            for (int it = 0; it < 8; it++) {
                int id = tid + it * 512;
                int r = id >> 7, n = id & 127;
                int gm = m0 + ph * 32 + r;
                if (gm < NN) {
                    float v = buf[r * BLD + n];
                    bool pos = g_yb[gm] != 0;
                    float t2 = pos ? -v : v;
                    float sp = fmaxf(t2, 0.f) + log1pf(expf(-fabsf(t2)));
                    if (pos) lp += sp; else ln += sp;
                }
            }
            __syncthreads();
        }
        #pragma unroll
        for (int o = 16; o; o >>= 1) {
            lp += __shfl_down_sync(0xffffffffu, lp, o);
            ln += __shfl_down_sync(0xffffffffu, ln, o);
        }
        if ((tid & 31) == 0) {
            atomicAdd(&g_lp, lp);
            atomicAdd(&g_ln, ln);
        }

        // merged finalization: last block computes loss, restores invariants
        __syncthreads();
        if (tid == 0) {
            __threadfence();
            int old = atomicAdd(&g_done, 1);
            if (old == (int)gridDim.x - 1) {
                __threadfence();
                float lpv = *((volatile float*)&g_lp);
                float lnv = *((volatile float*)&g_ln);
                int   np  = *((volatile int*)&g_npos);
                float l2 = lpv / (fmaxf((float)np, 1.f) * (float)DD);
                float l1 = lnv / (fmaxf((float)(NN - np), 1.f) * (float)DD);
                float loss = l1 + l2;
                if (lead > 0) {
                    for (int i = 0; i < lead && i < 16; i++) out[i] = loss;
                } else if (out_size > 0) {
                    out[0] = loss;
                }
                g_lp = 0.f; g_ln = 0.f; g_npos = 0; g_done = 0;
            }
        }
    }
}

__global__ void k_copy(float* __restrict__ out, int out_size) {
    int i = blockIdx.x * blockDim.x + threadIdx.x;
    if (i < out_size && i < OUT_ELEMS) out[i] = g_emb[i];
}

// ---------------- launch ----------------
extern "C" void kernel_launch(void* const* d_in, const int* in_sizes, int n_in,
                              void* d_out, int out_size) {
    const float* x = nullptr;
    const void*  edge = nullptr;
    const void*  yv = nullptr;
    const float* Ws[5] = {nullptr, nullptr, nullptr, nullptr, nullptr};
    const float* bs[2] = {nullptr, nullptr};
    int wi = 0, bi = 0;
    for (int i = 0; i < n_in; i++) {
        int sz = in_sizes[i];
        if (sz == NN * DD && !x) x = (const float*)d_in[i];
        else if (sz == 2 * NE && !edge) edge = d_in[i];
        else if (sz == NN && !yv) yv = d_in[i];
        else if (sz == DD * DD && wi < 5) Ws[wi++] = (const float*)d_in[i];
        else if (sz == DD && bi < 2) bs[bi++] = (const float*)d_in[i];
    }
    const float* b1l = bs[0];
    const float* b2l = bs[1];
    float* out = (float*)d_out;
    int lead = out_size - OUT_ELEMS;

    cudaFuncSetAttribute(k_gemm<0>, cudaFuncAttributeMaxDynamicSharedMemorySize, SMEM_G0);
    cudaFuncSetAttribute(k_gemm<1>, cudaFuncAttributeMaxDynamicSharedMemorySize, SMEM_G1);

    k_prep <<<EDGE_BLOCKS, 256>>>(yv, edge, Ws[0], Ws[1], Ws[2], Ws[3], Ws[4]);
    k_scan <<<SCAN_B, 256>>>();
    k_fill <<<EDGE_BLOCKS, 256>>>(edge);

    // layer 1
    k_mean<0><<<(NN + 7) / 8, 256>>>(x);
    k_gemm<0><<<GEMM_BLOCKS, 512, SMEM_G0>>>(x, b1l, out, lead, out_size);

    // layer 2 + fused decoder + loss + final
    k_mean<1><<<(NN + 7) / 8, 256>>>(nullptr);
    k_gemm<1><<<GEMM_BLOCKS, 512, SMEM_G1>>>(nullptr, b2l, out, lead, out_size);

    if (lead < 0) k_copy<<<(OUT_ELEMS + 255) / 256, 256>>>(out, out_size);
}

// round 13
// speedup vs baseline: 1.2484x; 1.0533x over previous
#include <cuda_runtime.h>
#include <cuda_bf16.h>
#include <mma.h>
#include <math.h>
#include <stdint.h>

using namespace nvcuda;

#define NN 50000
#define NE 800000
#define DD 128
#define OUT_ELEMS (NN * DD)
#define BM 128
#define GEMM_BLOCKS ((NN + BM - 1) / BM)
#define SCAN_B ((NN + 255) / 256)
#define EPT 4
#define EDGE_BLOCKS ((NE / EPT + 255) / 256)
#define ALD 40
#define BLD 136
#define AS_BYTES (2 * 2 * 128 * ALD * 2)            // 40960
#define BS_BYTES (2 * 2 * 32 * BLD * 2)             // 34816
#define EMB_BYTES (2 * 128 * BLD * 2)               // 69632
#define SMEM_G0 (AS_BYTES + BS_BYTES)               // 75776 (>= 128*BLD*4 = 69632)
#define SMEM_G1 (AS_BYTES + BS_BYTES + EMB_BYTES)   // 145408

// ---------------- device scratch (zero at load; every call restores zeros) --------
__device__ __align__(16) float g_mean[NN * DD];
__device__ __align__(16) float g_h[NN * DD];
__device__ __align__(16) float g_emb[NN * DD];     // only used when lead < 0
__device__ int   g_deg[NN];
__device__ int   g_off[NN + 1];
__device__ int   g_cur[NN];
__device__ int   g_col[NE];
__device__ unsigned char g_yb[NN];
__device__ float g_lp;
__device__ float g_ln;
__device__ int   g_npos;
__device__ int   g_done;
__device__ unsigned long long g_lb[SCAN_B];
__device__ __align__(16) unsigned short g_Bimg[5][2][DD * DD];

// ---------------- fp32 -> bf16 hi/lo packing ----------------
__device__ __forceinline__ void split4(float4 v, uint2& hi, uint2& lo) {
    __nv_bfloat162 h0 = __float22bfloat162_rn(make_float2(v.x, v.y));
    __nv_bfloat162 h1 = __float22bfloat162_rn(make_float2(v.z, v.w));
    float2 f0 = __bfloat1622float2(h0);
    float2 f1 = __bfloat1622float2(h1);
    __nv_bfloat162 l0 = __float22bfloat162_rn(make_float2(v.x - f0.x, v.y - f0.y));
    __nv_bfloat162 l1 = __float22bfloat162_rn(make_float2(v.z - f1.x, v.w - f1.y));
    hi = make_uint2(*(uint32_t*)&h0, *(uint32_t*)&h1);
    lo = make_uint2(*(uint32_t*)&l0, *(uint32_t*)&l1);
}

// ---------------- per-block dtype detection ----------------
__device__ __forceinline__ int detect_e64(const void* edge) {
    __shared__ int s64;
    if (threadIdx.x == 0) s64 = 1;
    __syncthreads();
    if (threadIdx.x < 256) {
        long long v = ((const long long*)edge)[threadIdx.x];
        if (v < 0 || v >= NN) atomicAnd(&s64, 0);
    }
    __syncthreads();
    return s64;
}

__device__ __forceinline__ int edge_at(const void* edge, int idx, int e64) {
    if (e64) return (int)((const long long*)edge)[idx];
    return ((const int*)edge)[idx];
}

// ---------------- k_prep ----------------
__global__ void k_prep(const void* __restrict__ yv, const void* __restrict__ edge,
                       const float* __restrict__ W0, const float* __restrict__ W1,
                       const float* __restrict__ W2, const float* __restrict__ W3,
                       const float* __restrict__ W4) {
    __shared__ int s32;
    if (threadIdx.x == 0) s32 = 1;
    int e64 = detect_e64(edge);
    if (threadIdx.x < 64) {
        unsigned int w = ((const unsigned int*)yv)[threadIdx.x];
        if (w > 1u) atomicAnd(&s32, 0);
    }
    __syncthreads();
    int y32 = s32;

    int i = blockIdx.x * blockDim.x + threadIdx.x;
    int v = 0;
    if (i < NN) {
        if (y32) v = (((const int*)yv)[i] != 0) ? 1 : 0;
        else     v = (((const unsigned char*)yv)[i] != 0) ? 1 : 0;
        g_yb[i] = (unsigned char)v;
    }
    #pragma unroll
    for (int o = 16; o; o >>= 1) v += __shfl_down_sync(0xffffffffu, v, o);
    if ((threadIdx.x & 31) == 0 && v) atomicAdd(&g_npos, v);

    if (i < 5 * DD * DD) {
        int w = i / (DD * DD);
        int r = i % (DD * DD);
        const float* Wm = (w == 0) ? W0 : (w == 1) ? W1 : (w == 2) ? W2 : (w == 3) ? W3 : W4;
        float val = Wm[r];
        __nv_bfloat16 hi = __float2bfloat16(val);
        g_Bimg[w][0][r] = __bfloat16_as_ushort(hi);
        g_Bimg[w][1][r] = __bfloat16_as_ushort(__float2bfloat16(val - __bfloat162float(hi)));
    }

    int base = i * EPT;
    int d[EPT];
    #pragma unroll
    for (int j = 0; j < EPT; j++)
        d[j] = (base + j < NE) ? edge_at(edge, NE + base + j, e64) : -1;
    #pragma unroll
    for (int j = 0; j < EPT; j++)
        if (d[j] >= 0 && d[j] < NN) atomicAdd(&g_deg[d[j]], 1);
}

// ---------------- decoupled-lookback scan ----------------
__global__ void k_scan() {
    __shared__ int sh[256];
    __shared__ int s_ex;
    int b = blockIdx.x, t = threadIdx.x;
    int i = b * 256 + t;
    int v = (i < NN) ? g_deg[i] : 0;
    sh[t] = v;
    __syncthreads();
    for (int o = 1; o < 256; o <<= 1) {
        int add = (t >= o) ? sh[t - o] : 0;
        __syncthreads();
        sh[t] += add;
        __syncthreads();
    }
    int T = sh[255];
    if (t == 0) {
        if (b == 0) {
            atomicExch(&g_lb[0], (2ULL << 32) | (unsigned)T);
            s_ex = 0;
        } else {
            atomicExch(&g_lb[b], (1ULL << 32) | (unsigned)T);
            int ex = 0;
            for (int j = b - 1; j >= 0;) {
                unsigned long long w;
                do { w = atomicAdd(&g_lb[j], 0ULL); } while ((w >> 32) == 0ULL);
                if ((w >> 32) == 2ULL) { ex += (int)(unsigned)w; break; }
                ex += (int)(unsigned)w;
                j--;
            }
            atomicExch(&g_lb[b], (2ULL << 32) | (unsigned)(ex + T));
            s_ex = ex;
        }
    }
    __syncthreads();
    int ex = s_ex;
    if (i < NN) {
        int off = ex + sh[t] - v;
        g_off[i] = off;
        g_cur[i] = off;
        g_deg[i] = 0;
    }
    if (b == SCAN_B - 1 && t == 0) g_off[NN] = ex + T;
}

// ---------------- CSR fill ----------------
__global__ void k_fill(const void* __restrict__ edge) {
    int e64 = detect_e64(edge);
    int i = blockIdx.x * blockDim.x + threadIdx.x;
    if (i < SCAN_B) g_lb[i] = 0ULL;
    int base = i * EPT;
    int s[EPT], d[EPT];
    #pragma unroll
    for (int j = 0; j < EPT; j++) {
        if (base + j < NE) {
            d[j] = edge_at(edge, NE + base + j, e64);
            s[j] = edge_at(edge, base + j, e64);
        } else { d[j] = -1; s[j] = 0; }
    }
    #pragma unroll
    for (int j = 0; j < EPT; j++) {
        if (d[j] >= 0 && d[j] < NN && s[j] >= 0 && s[j] < NN) {
            int p = atomicAdd(&g_cur[d[j]], 1);
            g_col[p] = s[j];
        }
    }
}

// ---------------- mean aggregation: 1 warp per node ----------------
template <int SRC>
__global__ void k_mean(const float* __restrict__ feat) {
    int node = blockIdx.x * 8 + (threadIdx.x >> 5);
    int lane = threadIdx.x & 31;
    if (node >= NN) return;
    const float4* __restrict__ f = (const float4*)((SRC == 0) ? feat : (const float*)g_h);
    int s = g_off[node], e = g_off[node + 1];
    float4 acc = make_float4(0.f, 0.f, 0.f, 0.f);
    int k = s;
    for (; k + 8 <= e; k += 8) {
        int c[8];
        #pragma unroll
        for (int j = 0; j < 8; j++) c[j] = __ldg(&g_col[k + j]);
        float4 v[8];
        #pragma unroll
        for (int j = 0; j < 8; j++) v[j] = __ldg(&f[(size_t)c[j] * 32 + lane]);
        acc.x += ((v[0].x + v[1].x) + (v[2].x + v[3].x)) + ((v[4].x + v[5].x) + (v[6].x + v[7].x));
        acc.y += ((v[0].y + v[1].y) + (v[2].y + v[3].y)) + ((v[4].y + v[5].y) + (v[6].y + v[7].y));
        acc.z += ((v[0].z + v[1].z) + (v[2].z + v[3].z)) + ((v[4].z + v[5].z) + (v[6].z + v[7].z));
        acc.w += ((v[0].w + v[1].w) + (v[2].w + v[3].w)) + ((v[4].w + v[5].w) + (v[6].w + v[7].w));
    }
    for (; k < e; k++) {
        float4 v = __ldg(&f[(size_t)__ldg(&g_col[k]) * 32 + lane]);
        acc.x += v.x; acc.y += v.y; acc.z += v.z; acc.w += v.w;
    }
    float inv = 1.f / fmaxf((float)(e - s), 1.f);
    ((float4*)g_mean)[(size_t)node * 32 + lane] =
        make_float4(acc.x * inv, acc.y * inv, acc.z * inv, acc.w * inv);
}

// ---------------- double-buffered WMMA bf16x3 GEMM, BM=128, 512 threads -----------
typedef wmma::fragment<wmma::accumulator, 16, 16, 16, float> AccFrag;

struct Pref {
    float4 a[2];
    uint4  b[2];
};

__device__ __forceinline__ __nv_bfloat16* as_ptr(char* sdyn, int buf, int hl) {
    return (__nv_bfloat16*)sdyn + (size_t)(buf * 2 + hl) * 128 * ALD;
}
__device__ __forceinline__ __nv_bfloat16* bs_ptr(char* sdyn, int buf, int hl) {
    return (__nv_bfloat16*)(sdyn + AS_BYTES) + (size_t)(buf * 2 + hl) * 32 * BLD;
}
__device__ __forceinline__ __nv_bfloat16* emb_ptr(char* sdyn, int hl) {
    return (__nv_bfloat16*)(sdyn + AS_BYTES + BS_BYTES) + (size_t)hl * 128 * BLD;
}

__device__ __forceinline__ void pf_load(Pref& p, const float* __restrict__ Asrc,
                                        int wsel, int c, int m0, int tid) {
    #pragma unroll
    for (int it = 0; it < 2; it++) {
        int id = tid + it * 512;
        int row = id >> 3, q = id & 7;
        int gm = m0 + row;
        p.a[it] = (gm < NN) ? *(const float4*)&Asrc[(size_t)gm * DD + c * 32 + q * 4]
                            : make_float4(0.f, 0.f, 0.f, 0.f);
    }
    #pragma unroll
    for (int it = 0; it < 2; it++) {
        int k = tid >> 4, c16 = tid & 15;
        p.b[it] = ((const uint4*)&g_Bimg[wsel][it][(c * 32 + k) * DD])[c16];
    }
}

__device__ __forceinline__ void pf_store(const Pref& p, char* sdyn, int buf, int tid) {
    __nv_bfloat16* Ah = as_ptr(sdyn, buf, 0);
    __nv_bfloat16* Al = as_ptr(sdyn, buf, 1);
    #pragma unroll
    for (int it = 0; it < 2; it++) {
        int id = tid + it * 512;
        int row = id >> 3, q = id & 7;
        uint2 hi, lo;
        split4(p.a[it], hi, lo);
        *(uint2*)&Ah[row * ALD + q * 4] = hi;
        *(uint2*)&Al[row * ALD + q * 4] = lo;
    }
    #pragma unroll
    for (int it = 0; it < 2; it++) {
        __nv_bfloat16* B = bs_ptr(sdyn, buf, it);
        int k = tid >> 4, c16 = tid & 15;
        ((uint4*)&B[k * BLD])[c16] = p.b[it];
    }
}

__device__ __forceinline__ void mma_chunk(char* sdyn, int buf,
                                          AccFrag (&acc)[2][2], int warp_m, int warp_n) {
    __nv_bfloat16* Ah = as_ptr(sdyn, buf, 0);
    __nv_bfloat16* Al = as_ptr(sdyn, buf, 1);
    __nv_bfloat16* Bh = bs_ptr(sdyn, buf, 0);
    __nv_bfloat16* Bl = bs_ptr(sdyn, buf, 1);
    #pragma unroll
    for (int ks = 0; ks < 2; ks++) {
        wmma::fragment<wmma::matrix_a, 16, 16, 16, __nv_bfloat16, wmma::row_major> a_hi[2], a_lo[2];
        #pragma unroll
        for (int mt = 0; mt < 2; mt++) {
            int mr = (warp_m * 32 + mt * 16) * ALD + ks * 16;
            wmma::load_matrix_sync(a_hi[mt], &Ah[mr], ALD);
            wmma::load_matrix_sync(a_lo[mt], &Al[mr], ALD);
        }
        #pragma unroll
        for (int nt = 0; nt < 2; nt++) {
            int nb = warp_n * 32 + nt * 16;
            wmma::fragment<wmma::matrix_b, 16, 16, 16, __nv_bfloat16, wmma::row_major> b_hi, b_lo;
            wmma::load_matrix_sync(b_hi, &Bh[ks * 16 * BLD + nb], BLD);
            wmma::load_matrix_sync(b_lo, &Bl[ks * 16 * BLD + nb], BLD);
            #pragma unroll
            for (int mt = 0; mt < 2; mt++) {
                wmma::mma_sync(acc[mt][nt], a_hi[mt], b_hi, acc[mt][nt]);
                wmma::mma_sync(acc[mt][nt], a_hi[mt], b_lo, acc[mt][nt]);
                wmma::mma_sync(acc[mt][nt], a_lo[mt], b_hi, acc[mt][nt]);
            }
        }
    }
}

// decoder mma: A frags from smem emb image
__device__ __forceinline__ void mma_dec(char* sdyn, int buf, int c,
                                        AccFrag (&acc)[2][2], int warp_m, int warp_n) {
    __nv_bfloat16* Eh = emb_ptr(sdyn, 0);
    __nv_bfloat16* El = emb_ptr(sdyn, 1);
    __nv_bfloat16* Bh = bs_ptr(sdyn, buf, 0);
    __nv_bfloat16* Bl = bs_ptr(sdyn, buf, 1);
    #pragma unroll
    for (int ks = 0; ks < 2; ks++) {
        wmma::fragment<wmma::matrix_a, 16, 16, 16, __nv_bfloat16, wmma::row_major> a_hi[2], a_lo[2];
        #pragma unroll
        for (int mt = 0; mt < 2; mt++) {
            int mr = (warp_m * 32 + mt * 16) * BLD + c * 32 + ks * 16;
            wmma::load_matrix_sync(a_hi[mt], &Eh[mr], BLD);
            wmma::load_matrix_sync(a_lo[mt], &El[mr], BLD);
        }
        #pragma unroll
        for (int nt = 0; nt < 2; nt++) {
            int nb = warp_n * 32 + nt * 16;
            wmma::fragment<wmma::matrix_b, 16, 16, 16, __nv_bfloat16, wmma::row_major> b_hi, b_lo;
            wmma::load_matrix_sync(b_hi, &Bh[ks * 16 * BLD + nb], BLD);
            wmma::load_matrix_sync(b_lo, &Bl[ks * 16 * BLD + nb], BLD);
            #pragma unroll
            for (int mt = 0; mt < 2; mt++) {
                wmma::mma_sync(acc[mt][nt], a_hi[mt], b_hi, acc[mt][nt]);
                wmma::mma_sync(acc[mt][nt], a_hi[mt], b_lo, acc[mt][nt]);
                wmma::mma_sync(acc[mt][nt], a_lo[mt], b_hi, acc[mt][nt]);
            }
        }
    }
}

__device__ __forceinline__ void gemm_pipeline(
    char* sdyn,
    const float* __restrict__ src0, int wsel0,
    const float* __restrict__ src1, int wsel1,
    int m0, AccFrag (&acc)[2][2], int tid, int warp_m, int warp_n) {
    Pref p;
    pf_load(p, src0, wsel0, 0, m0, tid);
    const int T = 8;
    for (int t = 0; t < T; t++) {
        int buf = t & 1;
        pf_store(p, sdyn, buf, tid);
        __syncthreads();
        if (t + 1 < T) {
            const float* nptr = ((t + 1) >> 2) ? src1 : src0;
            int nwsel = ((t + 1) >> 2) ? wsel1 : wsel0;
            pf_load(p, nptr, nwsel, (t + 1) & 3, m0, tid);
        }
        mma_chunk(sdyn, buf, acc, warp_m, warp_n);
    }
    __syncthreads();
}

// store all 16 warps' acc frags into one 128 x BLD fp32 smem tile
__device__ __forceinline__ void store_frags(float* buf, AccFrag (&acc)[2][2],
                                            int warp_m, int warp_n) {
    #pragma unroll
    for (int mt = 0; mt < 2; mt++)
        #pragma unroll
        for (int nt = 0; nt < 2; nt++)
            wmma::store_matrix_sync(&buf[(warp_m * 32 + mt * 16) * BLD + warp_n * 32 + nt * 16],
                                    acc[mt][nt], BLD, wmma::mem_row_major);
}

// CFG=0: g_h = relu([g_mean | x] @ [W1l;W1r] + b1l)
// CFG=1: emb = [g_mean | g_h] @ [W2l;W2r] + b2l -> out (and smem); decoder+loss+final
template <int CFG>
__global__ void __launch_bounds__(512, 1)
k_gemm(const float* __restrict__ xparam, const float* __restrict__ bias,
       float* __restrict__ out, int lead, int out_size) {
    extern __shared__ char sdyn[];
    int tid = threadIdx.x;
    int wid = tid >> 5;
    int warp_m = wid & 3;
    int warp_n = wid >> 2;
    int m0 = blockIdx.x * BM;

    AccFrag acc[2][2];
    #pragma unroll
    for (int mt = 0; mt < 2; mt++)
        #pragma unroll
        for (int nt = 0; nt < 2; nt++) wmma::fill_fragment(acc[mt][nt], 0.f);

    if (CFG == 0)
        gemm_pipeline(sdyn, g_mean, 0, xparam, 1, m0, acc, tid, warp_m, warp_n);
    else
        gemm_pipeline(sdyn, g_mean, 2, g_h, 3, m0, acc, tid, warp_m, warp_n);

    // ---------------- epilogue (single phase): bias (+relu / emb image) ---------
    float* buf = (float*)sdyn;   // 128 x BLD fp32 = 69632B (fits in As+Bs region)
    __nv_bfloat16* Eh = emb_ptr(sdyn, 0);
    __nv_bfloat16* El = emb_ptr(sdyn, 1);
    store_frags(buf, acc, warp_m, warp_n);
    __syncthreads();
    bool out_vec = (lead >= 0) && ((lead & 3) == 0);
    #pragma unroll
    for (int it = 0; it < 8; it++) {
        int id = tid + it * 512;
        int r = id >> 5, n = (id & 31) * 4;
        int gm = m0 + r;
        float4 v = *(float4*)&buf[r * BLD + n];
        float4 bv = *(const float4*)&bias[n];
        v.x += bv.x; v.y += bv.y; v.z += bv.z; v.w += bv.w;
        if (CFG == 0) {
            if (gm < NN) {
                v.x = fmaxf(v.x, 0.f); v.y = fmaxf(v.y, 0.f);
                v.z = fmaxf(v.z, 0.f); v.w = fmaxf(v.w, 0.f);
                *(float4*)&g_h[(size_t)gm * DD + n] = v;
            }
        } else {
            uint2 hi, lo;
            split4(v, hi, lo);
            *(uint2*)&Eh[r * BLD + n] = hi;
            *(uint2*)&El[r * BLD + n] = lo;
            if (gm < NN) {
                if (lead >= 0) {
                    size_t o = (size_t)lead + (size_t)gm * DD + n;
                    if (out_vec) {
                        *(float4*)&out[o] = v;
                    } else {            // lead misaligns float4 (e.g. lead=1)
                        out[o + 0] = v.x; out[o + 1] = v.y;
                        out[o + 2] = v.z; out[o + 3] = v.w;
                    }
                } else {
                    *(float4*)&g_emb[(size_t)gm * DD + n] = v;
                }
            }
        }
    }
    __syncthreads();

    // ---------------- fused decoder (A from smem) + BCE loss + final (CFG==1) ----
    if (CFG == 1) {
        #pragma unroll
        for (int mt = 0; mt < 2; mt++)
            #pragma unroll
            for (int nt = 0; nt < 2; nt++) wmma::fill_fragment(acc[mt][nt], 0.f);

        uint4 pb[2];
        {
            int k = tid >> 4, c16 = tid & 15;
            pb[0] = ((const uint4*)&g_Bimg[4][0][k * DD])[c16];
            pb[1] = ((const uint4*)&g_Bimg[4][1][k * DD])[c16];
        }
        for (int t = 0; t < 4; t++) {
            int bf = t & 1;
            {
                int k = tid >> 4, c16 = tid & 15;
                ((uint4*)&bs_ptr(sdyn, bf, 0)[k * BLD])[c16] = pb[0];
                ((uint4*)&bs_ptr(sdyn, bf, 1)[k * BLD])[c16] = pb[1];
            }
            __syncthreads();
            if (t + 1 < 4) {
                int k = tid >> 4, c16 = tid & 15;
                pb[0] = ((const uint4*)&g_Bimg[4][0][((t + 1) * 32 + k) * DD])[c16];
                pb[1] = ((const uint4*)&g_Bimg[4][1][((t + 1) * 32 + k) * DD])[c16];
            }
            mma_dec(sdyn, bf, t, acc, warp_m, warp_n);
            __syncthreads();
        }

        store_frags(buf, acc, warp_m, warp_n);
        __syncthreads();
        float lp = 0.f, ln = 0.f;
        #pragma unroll
        for (int it = 0; it < 8; it++) {
            int id = tid + it * 512;
            int r = id >> 5, n = (id & 31) * 4;
            int gm = m0 + r;
            if (gm < NN) {
                float4 v = *(float4*)&buf[r * BLD + n];
                bool pos = g_yb[gm] != 0;
                float vv[4] = {v.x, v.y, v.z, v.w};
                #pragma unroll
                for (int j = 0; j < 4; j++) {
                    float t2 = pos ? -vv[j] : vv[j];
                    float sp = fmaxf(t2, 0.f) + log1pf(expf(-fabsf(t2)));
                    if (pos) lp += sp; else ln += sp;
                }
            }
        }
        #pragma unroll
        for (int o = 16; o; o >>= 1) {
            lp += __shfl_down_sync(0xffffffffu, lp, o);
            ln += __shfl_down_sync(0xffffffffu, ln, o);
        }
        if ((tid & 31) == 0) {
            atomicAdd(&g_lp, lp);
            atomicAdd(&g_ln, ln);
        }

        __syncthreads();
        if (tid == 0) {
            __threadfence();
            int old = atomicAdd(&g_done, 1);
            if (old == (int)gridDim.x - 1) {
                __threadfence();
                float lpv = *((volatile float*)&g_lp);
                float lnv = *((volatile float*)&g_ln);
                int   np  = *((volatile int*)&g_npos);
                float l2 = lpv / (fmaxf((float)np, 1.f) * (float)DD);
                float l1 = lnv / (fmaxf((float)(NN - np), 1.f) * (float)DD);
                float loss = l1 + l2;
                if (lead > 0) {
                    for (int i = 0; i < lead && i < 16; i++) out[i] = loss;
                } else if (out_size > 0) {
                    out[0] = loss;
                }
                g_lp = 0.f; g_ln = 0.f; g_npos = 0; g_done = 0;
            }
        }
    }
}

__global__ void k_copy(float* __restrict__ out, int out_size) {
    int i = blockIdx.x * blockDim.x + threadIdx.x;
    if (i < out_size && i < OUT_ELEMS) out[i] = g_emb[i];
}

// ---------------- launch ----------------
extern "C" void kernel_launch(void* const* d_in, const int* in_sizes, int n_in,
                              void* d_out, int out_size) {
    const float* x = nullptr;
    const void*  edge = nullptr;
    const void*  yv = nullptr;
    const float* Ws[5] = {nullptr, nullptr, nullptr, nullptr, nullptr};
    const float* bs[2] = {nullptr, nullptr};
    int wi = 0, bi = 0;
    for (int i = 0; i < n_in; i++) {
        int sz = in_sizes[i];
        if (sz == NN * DD && !x) x = (const float*)d_in[i];
        else if (sz == 2 * NE && !edge) edge = d_in[i];
        else if (sz == NN && !yv) yv = d_in[i];
        else if (sz == DD * DD && wi < 5) Ws[wi++] = (const float*)d_in[i];
        else if (sz == DD && bi < 2) bs[bi++] = (const float*)d_in[i];
    }
    const float* b1l = bs[0];
    const float* b2l = bs[1];
    float* out = (float*)d_out;
    int lead = out_size - OUT_ELEMS;

    cudaFuncSetAttribute(k_gemm<0>, cudaFuncAttributeMaxDynamicSharedMemorySize, SMEM_G0);
    cudaFuncSetAttribute(k_gemm<1>, cudaFuncAttributeMaxDynamicSharedMemorySize, SMEM_G1);

    k_prep <<<EDGE_BLOCKS, 256>>>(yv, edge, Ws[0], Ws[1], Ws[2], Ws[3], Ws[4]);
    k_scan <<<SCAN_B, 256>>>();
    k_fill <<<EDGE_BLOCKS, 256>>>(edge);

    // layer 1
    k_mean<0><<<(NN + 7) / 8, 256>>>(x);
    k_gemm<0><<<GEMM_BLOCKS, 512, SMEM_G0>>>(x, b1l, out, lead, out_size);

    // layer 2 + fused decoder + loss + final
    k_mean<1><<<(NN + 7) / 8, 256>>>(nullptr);
    k_gemm<1><<<GEMM_BLOCKS, 512, SMEM_G1>>>(nullptr, b2l, out, lead, out_size);

    if (lead < 0) k_copy<<<(OUT_ELEMS + 255) / 256, 256>>>(out, out_size);
}

// round 14
// speedup vs baseline: 1.3025x; 1.0434x over previous
#include <cuda_runtime.h>
#include <cuda_bf16.h>
#include <mma.h>
#include <math.h>
#include <stdint.h>

using namespace nvcuda;

#define NN 50000
#define NE 800000
#define DD 128
#define OUT_ELEMS (NN * DD)
#define BM 128
#define GEMM_BLOCKS ((NN + BM - 1) / BM)
#define SCAN_B ((NN + 255) / 256)
#define EPT 4
#define EDGE_BLOCKS ((NE / EPT + 255) / 256)
#define ALD 72                                      // K=64 chunk + pad
#define BLD 136
#define AS_BYTES (2 * 2 * 128 * ALD * 2)            // 73728
#define BS_BYTES (2 * 2 * 64 * BLD * 2)             // 69632
#define EMB_BYTES (2 * 128 * BLD * 2)               // 69632
#define SMEM_G0 (AS_BYTES + BS_BYTES)               // 143360 (>= 128*BLD*4 = 69632)
#define SMEM_G1 (AS_BYTES + BS_BYTES + EMB_BYTES)   // 212992

// ---------------- device scratch (zero at load; every call restores zeros) --------
__device__ __align__(16) float g_mean[NN * DD];
__device__ __align__(16) float g_h[NN * DD];
__device__ __align__(16) float g_emb[NN * DD];     // only used when lead < 0
__device__ int   g_deg[NN];
__device__ int   g_off[NN + 1];
__device__ int   g_cur[NN];
__device__ int   g_col[NE];
__device__ unsigned char g_yb[NN];
__device__ float g_lp;
__device__ float g_ln;
__device__ int   g_npos;
__device__ int   g_done;
__device__ unsigned long long g_lb[SCAN_B];
__device__ __align__(16) unsigned short g_Bimg[5][2][DD * DD];

// ---------------- fp32 -> bf16 hi/lo packing ----------------
__device__ __forceinline__ void split4(float4 v, uint2& hi, uint2& lo) {
    __nv_bfloat162 h0 = __float22bfloat162_rn(make_float2(v.x, v.y));
    __nv_bfloat162 h1 = __float22bfloat162_rn(make_float2(v.z, v.w));
    float2 f0 = __bfloat1622float2(h0);
    float2 f1 = __bfloat1622float2(h1);
    __nv_bfloat162 l0 = __float22bfloat162_rn(make_float2(v.x - f0.x, v.y - f0.y));
    __nv_bfloat162 l1 = __float22bfloat162_rn(make_float2(v.z - f1.x, v.w - f1.y));
    hi = make_uint2(*(uint32_t*)&h0, *(uint32_t*)&h1);
    lo = make_uint2(*(uint32_t*)&l0, *(uint32_t*)&l1);
}

// ---------------- per-block dtype detection ----------------
__device__ __forceinline__ int detect_e64(const void* edge) {
    __shared__ int s64;
    if (threadIdx.x == 0) s64 = 1;
    __syncthreads();
    if (threadIdx.x < 256) {
        long long v = ((const long long*)edge)[threadIdx.x];
        if (v < 0 || v >= NN) atomicAnd(&s64, 0);
    }
    __syncthreads();
    return s64;
}

__device__ __forceinline__ int edge_at(const void* edge, int idx, int e64) {
    if (e64) return (int)((const long long*)edge)[idx];
    return ((const int*)edge)[idx];
}

// ---------------- k_prep ----------------
__global__ void k_prep(const void* __restrict__ yv, const void* __restrict__ edge,
                       const float* __restrict__ W0, const float* __restrict__ W1,
                       const float* __restrict__ W2, const float* __restrict__ W3,
                       const float* __restrict__ W4) {
    __shared__ int s32;
    if (threadIdx.x == 0) s32 = 1;
    int e64 = detect_e64(edge);
    if (threadIdx.x < 64) {
        unsigned int w = ((const unsigned int*)yv)[threadIdx.x];
        if (w > 1u) atomicAnd(&s32, 0);
    }
    __syncthreads();
    int y32 = s32;

    int i = blockIdx.x * blockDim.x + threadIdx.x;
    int v = 0;
    if (i < NN) {
        if (y32) v = (((const int*)yv)[i] != 0) ? 1 : 0;
        else     v = (((const unsigned char*)yv)[i] != 0) ? 1 : 0;
        g_yb[i] = (unsigned char)v;
    }
    #pragma unroll
    for (int o = 16; o; o >>= 1) v += __shfl_down_sync(0xffffffffu, v, o);
    if ((threadIdx.x & 31) == 0 && v) atomicAdd(&g_npos, v);

    if (i < 5 * DD * DD) {
        int w = i / (DD * DD);
        int r = i % (DD * DD);
        const float* Wm = (w == 0) ? W0 : (w == 1) ? W1 : (w == 2) ? W2 : (w == 3) ? W3 : W4;
        float val = Wm[r];
        __nv_bfloat16 hi = __float2bfloat16(val);
        g_Bimg[w][0][r] = __bfloat16_as_ushort(hi);
        g_Bimg[w][1][r] = __bfloat16_as_ushort(__float2bfloat16(val - __bfloat162float(hi)));
    }

    int base = i * EPT;
    int d[EPT];
    #pragma unroll
    for (int j = 0; j < EPT; j++)
        d[j] = (base + j < NE) ? edge_at(edge, NE + base + j, e64) : -1;
    #pragma unroll
    for (int j = 0; j < EPT; j++)
        if (d[j] >= 0 && d[j] < NN) atomicAdd(&g_deg[d[j]], 1);
}

// ---------------- decoupled-lookback scan ----------------
__global__ void k_scan() {
    __shared__ int sh[256];
    __shared__ int s_ex;
    int b = blockIdx.x, t = threadIdx.x;
    int i = b * 256 + t;
    int v = (i < NN) ? g_deg[i] : 0;
    sh[t] = v;
    __syncthreads();
    for (int o = 1; o < 256; o <<= 1) {
        int add = (t >= o) ? sh[t - o] : 0;
        __syncthreads();
        sh[t] += add;
        __syncthreads();
    }
    int T = sh[255];
    if (t == 0) {
        if (b == 0) {
            atomicExch(&g_lb[0], (2ULL << 32) | (unsigned)T);
            s_ex = 0;
        } else {
            atomicExch(&g_lb[b], (1ULL << 32) | (unsigned)T);
            int ex = 0;
            for (int j = b - 1; j >= 0;) {
                unsigned long long w;
                do { w = atomicAdd(&g_lb[j], 0ULL); } while ((w >> 32) == 0ULL);
                if ((w >> 32) == 2ULL) { ex += (int)(unsigned)w; break; }
                ex += (int)(unsigned)w;
                j--;
            }
            atomicExch(&g_lb[b], (2ULL << 32) | (unsigned)(ex + T));
            s_ex = ex;
        }
    }
    __syncthreads();
    int ex = s_ex;
    if (i < NN) {
        int off = ex + sh[t] - v;
        g_off[i] = off;
        g_cur[i] = off;
        g_deg[i] = 0;
    }
    if (b == SCAN_B - 1 && t == 0) g_off[NN] = ex + T;
}

// ---------------- CSR fill ----------------
__global__ void k_fill(const void* __restrict__ edge) {
    int e64 = detect_e64(edge);
    int i = blockIdx.x * blockDim.x + threadIdx.x;
    if (i < SCAN_B) g_lb[i] = 0ULL;
    int base = i * EPT;
    int s[EPT], d[EPT];
    #pragma unroll
    for (int j = 0; j < EPT; j++) {
        if (base + j < NE) {
            d[j] = edge_at(edge, NE + base + j, e64);
            s[j] = edge_at(edge, base + j, e64);
        } else { d[j] = -1; s[j] = 0; }
    }
    #pragma unroll
    for (int j = 0; j < EPT; j++) {
        if (d[j] >= 0 && d[j] < NN && s[j] >= 0 && s[j] < NN) {
            int p = atomicAdd(&g_cur[d[j]], 1);
            g_col[p] = s[j];
        }
    }
}

// ---------------- mean aggregation: 1 warp per node ----------------
template <int SRC>
__global__ void k_mean(const float* __restrict__ feat) {
    int node = blockIdx.x * 8 + (threadIdx.x >> 5);
    int lane = threadIdx.x & 31;
    if (node >= NN) return;
    const float4* __restrict__ f = (const float4*)((SRC == 0) ? feat : (const float*)g_h);
    int s = g_off[node], e = g_off[node + 1];
    float4 acc = make_float4(0.f, 0.f, 0.f, 0.f);
    int k = s;
    for (; k + 8 <= e; k += 8) {
        int c[8];
        #pragma unroll
        for (int j = 0; j < 8; j++) c[j] = __ldg(&g_col[k + j]);
        float4 v[8];
        #pragma unroll
        for (int j = 0; j < 8; j++) v[j] = __ldg(&f[(size_t)c[j] * 32 + lane]);
        acc.x += ((v[0].x + v[1].x) + (v[2].x + v[3].x)) + ((v[4].x + v[5].x) + (v[6].x + v[7].x));
        acc.y += ((v[0].y + v[1].y) + (v[2].y + v[3].y)) + ((v[4].y + v[5].y) + (v[6].y + v[7].y));
        acc.z += ((v[0].z + v[1].z) + (v[2].z + v[3].z)) + ((v[4].z + v[5].z) + (v[6].z + v[7].z));
        acc.w += ((v[0].w + v[1].w) + (v[2].w + v[3].w)) + ((v[4].w + v[5].w) + (v[6].w + v[7].w));
    }
    for (; k < e; k++) {
        float4 v = __ldg(&f[(size_t)__ldg(&g_col[k]) * 32 + lane]);
        acc.x += v.x; acc.y += v.y; acc.z += v.z; acc.w += v.w;
    }
    float inv = 1.f / fmaxf((float)(e - s), 1.f);
    ((float4*)g_mean)[(size_t)node * 32 + lane] =
        make_float4(acc.x * inv, acc.y * inv, acc.z * inv, acc.w * inv);
}

// ---------------- double-buffered WMMA bf16x3 GEMM, K=64 chunks -----------
typedef wmma::fragment<wmma::accumulator, 16, 16, 16, float> AccFrag;

struct Pref {
    float4 a[4];
    uint4  b[4];
};

__device__ __forceinline__ __nv_bfloat16* as_ptr(char* sdyn, int buf, int hl) {
    return (__nv_bfloat16*)sdyn + (size_t)(buf * 2 + hl) * 128 * ALD;
}
__device__ __forceinline__ __nv_bfloat16* bs_ptr(char* sdyn, int buf, int hl) {
    return (__nv_bfloat16*)(sdyn + AS_BYTES) + (size_t)(buf * 2 + hl) * 64 * BLD;
}
__device__ __forceinline__ __nv_bfloat16* emb_ptr(char* sdyn, int hl) {
    return (__nv_bfloat16*)(sdyn + AS_BYTES + BS_BYTES) + (size_t)hl * 128 * BLD;
}

// stage one K=64 chunk: A = 128x64 fp32 (2048 float4), B = 64x128 bf16 x2 images
__device__ __forceinline__ void pf_load(Pref& p, const float* __restrict__ Asrc,
                                        int wsel, int c, int m0, int tid) {
    #pragma unroll
    for (int it = 0; it < 4; it++) {
        int id = tid + it * 512;
        int row = id >> 4, q = id & 15;
        int gm = m0 + row;
        p.a[it] = (gm < NN) ? *(const float4*)&Asrc[(size_t)gm * DD + c * 64 + q * 4]
                            : make_float4(0.f, 0.f, 0.f, 0.f);
    }
    #pragma unroll
    for (int hl = 0; hl < 2; hl++)
        #pragma unroll
        for (int half = 0; half < 2; half++) {
            int id = tid + half * 512;        // 1024 uint4 per hl image
            int k = id >> 4, c16 = id & 15;
            p.b[hl * 2 + half] =
                ((const uint4*)&g_Bimg[wsel][hl][(c * 64 + k) * DD])[c16];
        }
}

__device__ __forceinline__ void pf_store(const Pref& p, char* sdyn, int buf, int tid) {
    __nv_bfloat16* Ah = as_ptr(sdyn, buf, 0);
    __nv_bfloat16* Al = as_ptr(sdyn, buf, 1);
    #pragma unroll
    for (int it = 0; it < 4; it++) {
        int id = tid + it * 512;
        int row = id >> 4, q = id & 15;
        uint2 hi, lo;
        split4(p.a[it], hi, lo);
        *(uint2*)&Ah[row * ALD + q * 4] = hi;
        *(uint2*)&Al[row * ALD + q * 4] = lo;
    }
    #pragma unroll
    for (int hl = 0; hl < 2; hl++) {
        __nv_bfloat16* B = bs_ptr(sdyn, buf, hl);
        #pragma unroll
        for (int half = 0; half < 2; half++) {
            int id = tid + half * 512;
            int k = id >> 4, c16 = id & 15;
            ((uint4*)&B[k * BLD])[c16] = p.b[hl * 2 + half];
        }
    }
}

__device__ __forceinline__ void mma_chunk(char* sdyn, int buf,
                                          AccFrag (&acc)[2][2], int warp_m, int warp_n) {
    __nv_bfloat16* Ah = as_ptr(sdyn, buf, 0);
    __nv_bfloat16* Al = as_ptr(sdyn, buf, 1);
    __nv_bfloat16* Bh = bs_ptr(sdyn, buf, 0);
    __nv_bfloat16* Bl = bs_ptr(sdyn, buf, 1);
    #pragma unroll
    for (int ks = 0; ks < 4; ks++) {
        wmma::fragment<wmma::matrix_a, 16, 16, 16, __nv_bfloat16, wmma::row_major> a_hi[2], a_lo[2];
        #pragma unroll
        for (int mt = 0; mt < 2; mt++) {
            int mr = (warp_m * 32 + mt * 16) * ALD + ks * 16;
            wmma::load_matrix_sync(a_hi[mt], &Ah[mr], ALD);
            wmma::load_matrix_sync(a_lo[mt], &Al[mr], ALD);
        }
        #pragma unroll
        for (int nt = 0; nt < 2; nt++) {
            int nb = warp_n * 32 + nt * 16;
            wmma::fragment<wmma::matrix_b, 16, 16, 16, __nv_bfloat16, wmma::row_major> b_hi, b_lo;
            wmma::load_matrix_sync(b_hi, &Bh[ks * 16 * BLD + nb], BLD);
            wmma::load_matrix_sync(b_lo, &Bl[ks * 16 * BLD + nb], BLD);
            #pragma unroll
            for (int mt = 0; mt < 2; mt++) {
                wmma::mma_sync(acc[mt][nt], a_hi[mt], b_hi, acc[mt][nt]);
                wmma::mma_sync(acc[mt][nt], a_hi[mt], b_lo, acc[mt][nt]);
                wmma::mma_sync(acc[mt][nt], a_lo[mt], b_hi, acc[mt][nt]);
            }
        }
    }
}

// decoder mma: A frags from smem emb image (BLD leading dim), K=64 chunk c
__device__ __forceinline__ void mma_dec(char* sdyn, int buf, int c,
                                        AccFrag (&acc)[2][2], int warp_m, int warp_n) {
    __nv_bfloat16* Eh = emb_ptr(sdyn, 0);
    __nv_bfloat16* El = emb_ptr(sdyn, 1);
    __nv_bfloat16* Bh = bs_ptr(sdyn, buf, 0);
    __nv_bfloat16* Bl = bs_ptr(sdyn, buf, 1);
    #pragma unroll
    for (int ks = 0; ks < 4; ks++) {
        wmma::fragment<wmma::matrix_a, 16, 16, 16, __nv_bfloat16, wmma::row_major> a_hi[2], a_lo[2];
        #pragma unroll
        for (int mt = 0; mt < 2; mt++) {
            int mr = (warp_m * 32 + mt * 16) * BLD + c * 64 + ks * 16;
            wmma::load_matrix_sync(a_hi[mt], &Eh[mr], BLD);
            wmma::load_matrix_sync(a_lo[mt], &El[mr], BLD);
        }
        #pragma unroll
        for (int nt = 0; nt < 2; nt++) {
            int nb = warp_n * 32 + nt * 16;
            wmma::fragment<wmma::matrix_b, 16, 16, 16, __nv_bfloat16, wmma::row_major> b_hi, b_lo;
            wmma::load_matrix_sync(b_hi, &Bh[ks * 16 * BLD + nb], BLD);
            wmma::load_matrix_sync(b_lo, &Bl[ks * 16 * BLD + nb], BLD);
            #pragma unroll
            for (int mt = 0; mt < 2; mt++) {
                wmma::mma_sync(acc[mt][nt], a_hi[mt], b_hi, acc[mt][nt]);
                wmma::mma_sync(acc[mt][nt], a_hi[mt], b_lo, acc[mt][nt]);
                wmma::mma_sync(acc[mt][nt], a_lo[mt], b_hi, acc[mt][nt]);
            }
        }
    }
}

// pipelined accumulation over 2 sources x 2 K-chunks = 4 iterations
__device__ __forceinline__ void gemm_pipeline(
    char* sdyn,
    const float* __restrict__ src0, int wsel0,
    const float* __restrict__ src1, int wsel1,
    int m0, AccFrag (&acc)[2][2], int tid, int warp_m, int warp_n) {
    Pref p;
    pf_load(p, src0, wsel0, 0, m0, tid);
    const int T = 4;
    for (int t = 0; t < T; t++) {
        int buf = t & 1;
        pf_store(p, sdyn, buf, tid);
        __syncthreads();
        if (t + 1 < T) {
            const float* nptr = ((t + 1) >> 1) ? src1 : src0;
            int nwsel = ((t + 1) >> 1) ? wsel1 : wsel0;
            pf_load(p, nptr, nwsel, (t + 1) & 1, m0, tid);
        }
        mma_chunk(sdyn, buf, acc, warp_m, warp_n);
    }
    __syncthreads();
}

// store all 16 warps' acc frags into one 128 x BLD fp32 smem tile
__device__ __forceinline__ void store_frags(float* buf, AccFrag (&acc)[2][2],
                                            int warp_m, int warp_n) {
    #pragma unroll
    for (int mt = 0; mt < 2; mt++)
        #pragma unroll
        for (int nt = 0; nt < 2; nt++)
            wmma::store_matrix_sync(&buf[(warp_m * 32 + mt * 16) * BLD + warp_n * 32 + nt * 16],
                                    acc[mt][nt], BLD, wmma::mem_row_major);
}

// CFG=0: g_h = relu([g_mean | x] @ [W1l;W1r] + b1l)
// CFG=1: emb = [g_mean | g_h] @ [W2l;W2r] + b2l -> out (and smem); decoder+loss+final
template <int CFG>
__global__ void __launch_bounds__(512, 1)
k_gemm(const float* __restrict__ xparam, const float* __restrict__ bias,
       float* __restrict__ out, int lead, int out_size) {
    extern __shared__ char sdyn[];
    int tid = threadIdx.x;
    int wid = tid >> 5;
    int warp_m = wid & 3;
    int warp_n = wid >> 2;
    int m0 = blockIdx.x * BM;

    AccFrag acc[2][2];
    #pragma unroll
    for (int mt = 0; mt < 2; mt++)
        #pragma unroll
        for (int nt = 0; nt < 2; nt++) wmma::fill_fragment(acc[mt][nt], 0.f);

    if (CFG == 0)
        gemm_pipeline(sdyn, g_mean, 0, xparam, 1, m0, acc, tid, warp_m, warp_n);
    else
        gemm_pipeline(sdyn, g_mean, 2, g_h, 3, m0, acc, tid, warp_m, warp_n);

    // ---------------- epilogue (single phase): bias (+relu / emb image) ---------
    float* buf = (float*)sdyn;   // 128 x BLD fp32 = 69632B, inside As+Bs region
    __nv_bfloat16* Eh = emb_ptr(sdyn, 0);
    __nv_bfloat16* El = emb_ptr(sdyn, 1);
    store_frags(buf, acc, warp_m, warp_n);
    __syncthreads();
    bool out_vec = (lead >= 0) && ((lead & 3) == 0);
    #pragma unroll
    for (int it = 0; it < 8; it++) {
        int id = tid + it * 512;
        int r = id >> 5, n = (id & 31) * 4;
        int gm = m0 + r;
        float4 v = *(float4*)&buf[r * BLD + n];
        float4 bv = *(const float4*)&bias[n];
        v.x += bv.x; v.y += bv.y; v.z += bv.z; v.w += bv.w;
        if (CFG == 0) {
            if (gm < NN) {
                v.x = fmaxf(v.x, 0.f); v.y = fmaxf(v.y, 0.f);
                v.z = fmaxf(v.z, 0.f); v.w = fmaxf(v.w, 0.f);
                *(float4*)&g_h[(size_t)gm * DD + n] = v;
            }
        } else {
            uint2 hi, lo;
            split4(v, hi, lo);
            *(uint2*)&Eh[r * BLD + n] = hi;
            *(uint2*)&El[r * BLD + n] = lo;
            if (gm < NN) {
                if (lead >= 0) {
                    size_t o = (size_t)lead + (size_t)gm * DD + n;
                    if (out_vec) {
                        *(float4*)&out[o] = v;
                    } else {
                        out[o + 0] = v.x; out[o + 1] = v.y;
                        out[o + 2] = v.z; out[o + 3] = v.w;
                    }
                } else {
                    *(float4*)&g_emb[(size_t)gm * DD + n] = v;
                }
            }
        }
    }
    __syncthreads();

    // ---------------- fused decoder (A from smem) + BCE loss + final (CFG==1) ----
    if (CFG == 1) {
        #pragma unroll
        for (int mt = 0; mt < 2; mt++)
            #pragma unroll
            for (int nt = 0; nt < 2; nt++) wmma::fill_fragment(acc[mt][nt], 0.f);

        // B-only pipeline over 2 K=64 chunks of Wdec (wsel=4)
        uint4 pb[4];
        #pragma unroll
        for (int hl = 0; hl < 2; hl++)
            #pragma unroll
            for (int half = 0; half < 2; half++) {
                int id = tid + half * 512;
                int k = id >> 4, c16 = id & 15;
                pb[hl * 2 + half] = ((const uint4*)&g_Bimg[4][hl][k * DD])[c16];
            }
        for (int t = 0; t < 2; t++) {
            int bf = t & 1;
            #pragma unroll
            for (int hl = 0; hl < 2; hl++) {
                __nv_bfloat16* B = bs_ptr(sdyn, bf, hl);
                #pragma unroll
                for (int half = 0; half < 2; half++) {
                    int id = tid + half * 512;
                    int k = id >> 4, c16 = id & 15;
                    ((uint4*)&B[k * BLD])[c16] = pb[hl * 2 + half];
                }
            }
            __syncthreads();
            if (t + 1 < 2) {
                #pragma unroll
                for (int hl = 0; hl < 2; hl++)
                    #pragma unroll
                    for (int half = 0; half < 2; half++) {
                        int id = tid + half * 512;
                        int k = id >> 4, c16 = id & 15;
                        pb[hl * 2 + half] =
                            ((const uint4*)&g_Bimg[4][hl][(64 + k) * DD])[c16];
                    }
            }
            mma_dec(sdyn, bf, t, acc, warp_m, warp_n);
        }
        __syncthreads();

        store_frags(buf, acc, warp_m, warp_n);
        __syncthreads();
        float lp = 0.f, ln = 0.f;
        #pragma unroll
        for (int it = 0; it < 8; it++) {
            int id = tid + it * 512;
            int r = id >> 5, n = (id & 31) * 4;
            int gm = m0 + r;
            if (gm < NN) {
                float4 v = *(float4*)&buf[r * BLD + n];
                bool pos = g_yb[gm] != 0;
                float vv[4] = {v.x, v.y, v.z, v.w};
                #pragma unroll
                for (int j = 0; j < 4; j++) {
                    float t2 = pos ? -vv[j] : vv[j];
                    float sp = fmaxf(t2, 0.f) + log1pf(expf(-fabsf(t2)));
                    if (pos) lp += sp; else ln += sp;
                }
            }
        }
        #pragma unroll
        for (int o = 16; o; o >>= 1) {
            lp += __shfl_down_sync(0xffffffffu, lp, o);
            ln += __shfl_down_sync(0xffffffffu, ln, o);
        }
        if ((tid & 31) == 0) {
            atomicAdd(&g_lp, lp);
            atomicAdd(&g_ln, ln);
        }

        __syncthreads();
        if (tid == 0) {
            __threadfence();
            int old = atomicAdd(&g_done, 1);
            if (old == (int)gridDim.x - 1) {
                __threadfence();
                float lpv = *((volatile float*)&g_lp);
                float lnv = *((volatile float*)&g_ln);
                int   np  = *((volatile int*)&g_npos);
                float l2 = lpv / (fmaxf((float)np, 1.f) * (float)DD);
                float l1 = lnv / (fmaxf((float)(NN - np), 1.f) * (float)DD);
                float loss = l1 + l2;
                if (lead > 0) {
                    for (int i = 0; i < lead && i < 16; i++) out[i] = loss;
                } else if (out_size > 0) {
                    out[0] = loss;
                }
                g_lp = 0.f; g_ln = 0.f; g_npos = 0; g_done = 0;
            }
        }
    }
}

__global__ void k_copy(float* __restrict__ out, int out_size) {
    int i = blockIdx.x * blockDim.x + threadIdx.x;
    if (i < out_size && i < OUT_ELEMS) out[i] = g_emb[i];
}

// ---------------- launch ----------------
extern "C" void kernel_launch(void* const* d_in, const int* in_sizes, int n_in,
                              void* d_out, int out_size) {
    const float* x = nullptr;
    const void*  edge = nullptr;
    const void*  yv = nullptr;
    const float* Ws[5] = {nullptr, nullptr, nullptr, nullptr, nullptr};
    const float* bs[2] = {nullptr, nullptr};
    int wi = 0, bi = 0;
    for (int i = 0; i < n_in; i++) {
        int sz = in_sizes[i];
        if (sz == NN * DD && !x) x = (const float*)d_in[i];
        else if (sz == 2 * NE && !edge) edge = d_in[i];
        else if (sz == NN && !yv) yv = d_in[i];
        else if (sz == DD * DD && wi < 5) Ws[wi++] = (const float*)d_in[i];
        else if (sz == DD && bi < 2) bs[bi++] = (const float*)d_in[i];
    }
    const float* b1l = bs[0];
    const float* b2l = bs[1];
    float* out = (float*)d_out;
    int lead = out_size - OUT_ELEMS;

    cudaFuncSetAttribute(k_gemm<0>, cudaFuncAttributeMaxDynamicSharedMemorySize, SMEM_G0);
    cudaFuncSetAttribute(k_gemm<1>, cudaFuncAttributeMaxDynamicSharedMemorySize, SMEM_G1);

    k_prep <<<EDGE_BLOCKS, 256>>>(yv, edge, Ws[0], Ws[1], Ws[2], Ws[3], Ws[4]);
    k_scan <<<SCAN_B, 256>>>();
    k_fill <<<EDGE_BLOCKS, 256>>>(edge);

    // layer 1
    k_mean<0><<<(NN + 7) / 8, 256>>>(x);
    k_gemm<0><<<GEMM_BLOCKS, 512, SMEM_G0>>>(x, b1l, out, lead, out_size);

    // layer 2 + fused decoder + loss + final
    k_mean<1><<<(NN + 7) / 8, 256>>>(nullptr);
    k_gemm<1><<<GEMM_BLOCKS, 512, SMEM_G1>>>(nullptr, b2l, out, lead, out_size);

    if (lead < 0) k_copy<<<(OUT_ELEMS + 255) / 256, 256>>>(out, out_size);
}